// round 4
// baseline (speedup 1.0000x reference)
#include <cuda_runtime.h>
#include <cstdint>

#define CC 128
#define LL 9
#define EE 5
#define NMAX 10000
#define M3 165
#define M2 45
#define M1 9
#define MTOT (M3 + M2 + M1)   // 219

static __device__ int    d_cnt[EE];
static __device__ int    d_tileOff[EE + 1];
static __device__ int    d_nodeList[EE * NMAX];
static __device__ float4 d_S3[EE * CC * M3];
static __device__ float4 d_S2[EE * CC * M2];
static __device__ float4 d_S1[EE * CC * M1];
static __device__ float  d_Og[4 * (size_t)NMAX * CC];   // [slot][b][c], slot0=irrep0, 1..3=irrep1 d

#define INV_SQRT_C 0.08838834764831845f

// ---------------------------------------------------------------- init / bucketing
__global__ void k_init() {
    if (threadIdx.x < EE) d_cnt[threadIdx.x] = 0;
}

__global__ void k_assign(const float* __restrict__ attrs, int n) {
    int b = blockIdx.x * blockDim.x + threadIdx.x;
    if (b >= n) return;
    int e = 0; float best = -1.0f;
#pragma unroll
    for (int j = 0; j < EE; j++) {
        float v = attrs[b * EE + j];
        if (v > best) { best = v; e = j; }
    }
    int pos = atomicAdd(&d_cnt[e], 1);
    d_nodeList[e * NMAX + pos] = b;
}

__global__ void k_off() {
    d_tileOff[0] = 0;
    for (int e = 0; e < EE; e++)
        d_tileOff[e + 1] = d_tileOff[e] + (d_cnt[e] + 31) / 32;
}

// ---------------------------------------------------------------- coefficient build
// With one-hot attrs the whole contraction collapses per (e,c) to a degree-3
// polynomial in x[0..8]. Pre-symmetrize U3·w3 / U2·w2 / U1·w1 into monomial
// coefficient tables S3 (165 cubic), S2 (45 quadratic), S1 (9 linear), each a
// float4 over the 4 output d-slots (irrep0 scalar + irrep1 x/y/z).
__global__ void k_coeffs(const float* __restrict__ U3_0, const float* __restrict__ U2_0,
                         const float* __restrict__ U1_0,
                         const float* __restrict__ w3_0, const float* __restrict__ w2_0,
                         const float* __restrict__ w1_0,
                         const float* __restrict__ U3_1, const float* __restrict__ U2_1,
                         const float* __restrict__ U1_1,
                         const float* __restrict__ w3_1, const float* __restrict__ w2_1,
                         const float* __restrict__ w1_1) {
    int gid = blockIdx.x * blockDim.x + threadIdx.x;
    if (gid >= EE * CC * MTOT) return;
    int m  = gid % MTOT;
    int ec = gid / MTOT;
    int c  = ec % CC;
    int e  = ec / CC;

    if (m < M3) {
        // decode m -> (U<=V<=W)
        int U = 0, V = 0, W = 0, cnt = 0;
        for (int a = 0; a < LL; a++)
            for (int b = a; b < LL; b++)
                for (int g = b; g < LL; g++) {
                    if (cnt == m) { U = a; V = b; W = g; }
                    cnt++;
                }
        float wa0[10], wa1[12];
        for (int k = 0; k < 10; k++) wa0[k] = w3_0[(e * 10 + k) * CC + c];
        for (int k = 0; k < 12; k++) wa1[k] = w3_1[(e * 12 + k) * CC + c];
        float s0 = 0.f, s1 = 0.f, s2 = 0.f, s3 = 0.f;
        int pa[6] = {U, U, V, V, W, W};
        int pb[6] = {V, W, U, W, U, V};
        int pg[6] = {W, V, W, U, V, U};
        for (int p = 0; p < 6; p++) {
            int a = pa[p], b = pb[p], g = pg[p];
            const float* u30 = U3_0 + ((a * LL + b) * LL + g) * 10;
            for (int k = 0; k < 10; k++) s0 += u30[k] * wa0[k];
            for (int d = 0; d < 3; d++) {
                const float* u31 = U3_1 + (((d * LL + a) * LL + b) * LL + g) * 12;
                float acc = 0.f;
                for (int k = 0; k < 12; k++) acc += u31[k] * wa1[k];
                if (d == 0) s1 += acc; else if (d == 1) s2 += acc; else s3 += acc;
            }
        }
        float dup;
        if (U == V && V == W) dup = 1.0f / 6.0f;
        else if (U == V || V == W || U == W) dup = 0.5f;
        else dup = 1.0f;
        d_S3[(e * CC + c) * M3 + m] = make_float4(s0 * dup, s1 * dup, s2 * dup, s3 * dup);
    } else if (m < M3 + M2) {
        int mm = m - M3;
        int U = 0, V = 0, cnt = 0;
        for (int a = 0; a < LL; a++)
            for (int b = a; b < LL; b++) {
                if (cnt == mm) { U = a; V = b; }
                cnt++;
            }
        float wb0[3], wb1[4];
        for (int k = 0; k < 3; k++) wb0[k] = w2_0[(e * 3 + k) * CC + c];
        for (int k = 0; k < 4; k++) wb1[k] = w2_1[(e * 4 + k) * CC + c];
        float s0 = 0.f, s1 = 0.f, s2 = 0.f, s3 = 0.f;
        for (int p = 0; p < 2; p++) {
            int a = p ? V : U, b = p ? U : V;
            const float* u20 = U2_0 + (a * LL + b) * 3;
            for (int k = 0; k < 3; k++) s0 += u20[k] * wb0[k];
            for (int d = 0; d < 3; d++) {
                const float* u21 = U2_1 + ((d * LL + a) * LL + b) * 4;
                float acc = 0.f;
                for (int k = 0; k < 4; k++) acc += u21[k] * wb1[k];
                if (d == 0) s1 += acc; else if (d == 1) s2 += acc; else s3 += acc;
            }
        }
        float dup = (U == V) ? 0.5f : 1.0f;
        d_S2[(e * CC + c) * M2 + mm] = make_float4(s0 * dup, s1 * dup, s2 * dup, s3 * dup);
    } else {
        int u = m - M3 - M2;
        float s0 = U1_0[u] * w1_0[e * CC + c];
        float s1 = U1_1[0 * LL + u] * w1_1[e * CC + c];
        float s2 = U1_1[1 * LL + u] * w1_1[e * CC + c];
        float s3 = U1_1[2 * LL + u] * w1_1[e * CC + c];
        d_S1[(e * CC + c) * M1 + u] = make_float4(s0, s1, s2, s3);
    }
}

// ---------------------------------------------------------------- main contraction
// block: 128 threads = 4 warps. warp -> channel (blockIdx.x*4 + warp); lane -> node
// within the element-homogeneous 32-node tile blockIdx.y. All S-reads are
// warp-uniform broadcasts from shared memory.
__global__ __launch_bounds__(128) void k_main(const float* __restrict__ xfeat, int n) {
    int t = blockIdx.y;
    if (t >= d_tileOff[EE]) return;
    int e = 0;
    while (t >= d_tileOff[e + 1]) e++;

    int warp = threadIdx.x >> 5, lane = threadIdx.x & 31;
    int c = blockIdx.x * 4 + warp;

    __shared__ float4 sh[4][MTOT];
    {
        const float4* s3 = &d_S3[(e * CC + c) * M3];
        for (int i = lane; i < M3; i += 32) sh[warp][i] = s3[i];
        const float4* s2 = &d_S2[(e * CC + c) * M2];
        for (int i = lane; i < M2; i += 32) sh[warp][M3 + i] = s2[i];
        const float4* s1 = &d_S1[(e * CC + c) * M1];
        if (lane < M1) sh[warp][M3 + M2 + lane] = s1[lane];
    }
    __syncwarp();

    int lt = t - d_tileOff[e];
    int ni = lt * 32 + lane;
    bool valid = ni < d_cnt[e];
    int b = d_nodeList[e * NMAX + (valid ? ni : 0)];

    float x[9];
    const float* xp = xfeat + ((size_t)b * CC + c) * LL;
#pragma unroll
    for (int w = 0; w < 9; w++) x[w] = xp[w];

    float r0 = 0.f, r1 = 0.f, r2 = 0.f, r3 = 0.f;
    const float4* S = sh[warp];
    int m3 = 0, m2 = M3;
#pragma unroll
    for (int u = 0; u < 9; u++) {
#pragma unroll
        for (int v = u; v < 9; v++) {
            float p = x[u] * x[v];
            float4 q = S[m2++];
            float i0 = q.x, i1 = q.y, i2 = q.z, i3 = q.w;
#pragma unroll
            for (int w = v; w < 9; w++) {
                float4 s = S[m3++];
                float xw = x[w];
                i0 = fmaf(s.x, xw, i0);
                i1 = fmaf(s.y, xw, i1);
                i2 = fmaf(s.z, xw, i2);
                i3 = fmaf(s.w, xw, i3);
            }
            r0 = fmaf(p, i0, r0);
            r1 = fmaf(p, i1, r1);
            r2 = fmaf(p, i2, r2);
            r3 = fmaf(p, i3, r3);
        }
    }
#pragma unroll
    for (int u = 0; u < 9; u++) {
        float4 s = S[M3 + M2 + u];
        float xu = x[u];
        r0 = fmaf(s.x, xu, r0);
        r1 = fmaf(s.y, xu, r1);
        r2 = fmaf(s.z, xu, r2);
        r3 = fmaf(s.w, xu, r3);
    }

    if (valid) {
        size_t base = (size_t)b * CC + c;
        const size_t st = (size_t)NMAX * CC;
        d_Og[base]          = r0;
        d_Og[st + base]     = r1;
        d_Og[2 * st + base] = r2;
        d_Og[3 * st + base] = r3;
    }
}

// ---------------------------------------------------------------- linear + residual
// 4 GEMMs: Y_s = Og_s[N,128] @ W_s[128,128]; epilogue fuses *1/sqrt(C) + sc with the
// irrep-concat column mapping.
#define BM 64
#define BN 64
#define BK 16
__global__ __launch_bounds__(256) void k_lin(const float* __restrict__ lin0,
                                             const float* __restrict__ lin1,
                                             const float* __restrict__ sc,
                                             float* __restrict__ out, int n) {
    int s = blockIdx.z;
    const float* A = d_Og + (size_t)s * NMAX * CC;
    const float* B = (s == 0) ? lin0 : lin1;

    __shared__ float As[BM][BK + 1];
    __shared__ float Bs[BK][BN];

    int tid = threadIdx.x;
    int tr = tid / 16, tc = tid % 16;
    int rowBase = blockIdx.y * BM;
    int colBase = blockIdx.x * BN;

    float acc[4][4];
#pragma unroll
    for (int i = 0; i < 4; i++)
#pragma unroll
        for (int j = 0; j < 4; j++) acc[i][j] = 0.f;

    for (int k0 = 0; k0 < CC; k0 += BK) {
#pragma unroll
        for (int i = 0; i < 4; i++) {
            int idx = tid + i * 256;
            int m = idx / BK, kk = idx % BK;
            int gr = rowBase + m;
            As[m][kk] = (gr < n) ? A[(size_t)gr * CC + k0 + kk] : 0.f;
        }
#pragma unroll
        for (int i = 0; i < 4; i++) {
            int idx = tid + i * 256;
            int kk = idx / BN, j = idx % BN;
            Bs[kk][j] = B[(k0 + kk) * CC + colBase + j];
        }
        __syncthreads();
#pragma unroll
        for (int kk = 0; kk < BK; kk++) {
            float a[4];
#pragma unroll
            for (int i = 0; i < 4; i++) a[i] = As[tr * 4 + i][kk];
            float4 bv = *reinterpret_cast<const float4*>(&Bs[kk][tc * 4]);
            float bb[4] = {bv.x, bv.y, bv.z, bv.w};
#pragma unroll
            for (int i = 0; i < 4; i++)
#pragma unroll
                for (int j = 0; j < 4; j++) acc[i][j] = fmaf(a[i], bb[j], acc[i][j]);
        }
        __syncthreads();
    }

#pragma unroll
    for (int i = 0; i < 4; i++) {
        int row = rowBase + tr * 4 + i;
        if (row >= n) continue;
#pragma unroll
        for (int j = 0; j < 4; j++) {
            int jg = colBase + tc * 4 + j;
            int col = (s == 0) ? jg : (CC + jg * 3 + (s - 1));
            size_t o = (size_t)row * 512 + col;
            out[o] = acc[i][j] * INV_SQRT_C + sc[o];
        }
    }
}

// ---------------------------------------------------------------- launch
extern "C" void kernel_launch(void* const* d_in, const int* in_sizes, int n_in,
                              void* d_out, int out_size) {
    const float* node_feats = (const float*)d_in[0];
    const float* node_attrs = (const float*)d_in[1];
    const float* sc         = (const float*)d_in[2];
    const float* U3_0 = (const float*)d_in[3];
    const float* U2_0 = (const float*)d_in[4];
    const float* U1_0 = (const float*)d_in[5];
    const float* w3_0 = (const float*)d_in[6];
    const float* w2_0 = (const float*)d_in[7];
    const float* w1_0 = (const float*)d_in[8];
    const float* U3_1 = (const float*)d_in[9];
    const float* U2_1 = (const float*)d_in[10];
    const float* U1_1 = (const float*)d_in[11];
    const float* w3_1 = (const float*)d_in[12];
    const float* w2_1 = (const float*)d_in[13];
    const float* w1_1 = (const float*)d_in[14];
    const float* lin_w0 = (const float*)d_in[15];
    const float* lin_w1 = (const float*)d_in[16];

    int n = in_sizes[0] / (CC * LL);

    k_init<<<1, 32>>>();
    k_assign<<<(n + 255) / 256, 256>>>(node_attrs, n);
    k_off<<<1, 1>>>();

    int work = EE * CC * MTOT;
    k_coeffs<<<(work + 255) / 256, 256>>>(U3_0, U2_0, U1_0, w3_0, w2_0, w1_0,
                                          U3_1, U2_1, U1_1, w3_1, w2_1, w1_1);

    int maxT = (n + 31) / 32 + EE;
    k_main<<<dim3(CC / 4, maxT), 128>>>(node_feats, n);

    dim3 g(CC / BN, (n + BM - 1) / BM, 4);
    k_lin<<<g, 256>>>(lin_w0, lin_w1, sc, (float*)d_out, n);
}

// round 5
// speedup vs baseline: 1.3726x; 1.3726x over previous
#include <cuda_runtime.h>
#include <cstdint>

#define CC 128
#define LL 9
#define EE 5
#define NMAX 10000
#define M3 165
#define M2 45
#define M1 9
#define MTOT (M3 + M2 + M1)   // 219
#define INV_SQRT_C 0.08838834764831845f

typedef unsigned long long u64;

// packed f32x2 helpers (SASS FFMA2 — only via PTX)
#define FMA2(d, a, b, c) asm("fma.rn.f32x2 %0, %1, %2, %3;" : "=l"(d) : "l"(a), "l"(b), "l"(c))
#define SPLAT2(d, s)     asm("mov.b64 %0, {%1, %1};" : "=l"(d) : "r"(__float_as_uint(s)))
#define UNPACK2(lo, hi, v) do { unsigned _lo, _hi; \
    asm("mov.b64 {%0, %1}, %2;" : "=r"(_lo), "=r"(_hi) : "l"(v)); \
    lo = __uint_as_float(_lo); hi = __uint_as_float(_hi); } while (0)

static __device__ int    d_cnt[EE];
static __device__ int    d_off[EE + 1];       // exact prefix of counts
static __device__ int    d_tileOff[EE + 1];   // prefix of 64-node tiles
static __device__ int    d_nodeList[EE * NMAX];
static __device__ int    d_nodeC[NMAX];       // compact pos -> node id
static __device__ float4 d_S3[EE * CC * M3];
static __device__ float4 d_S2[EE * CC * M2];
static __device__ float4 d_S1[EE * CC * M1];
static __device__ float  d_Og[4 * (size_t)CC * NMAX];  // [slot][c][pos]
// symmetrized U tables
static __device__ int   d_m3u[M3], d_m3v[M3], d_m3w[M3];
static __device__ int   d_m2u[M2], d_m2v[M2];
static __device__ float d_T30[M3 * 10];
static __device__ float d_T31[3 * M3 * 12];
static __device__ float d_T20[M2 * 3];
static __device__ float d_T21[3 * M2 * 4];

// ---------------------------------------------------------------- bucketing
__global__ void k_init() {
    if (threadIdx.x < EE) d_cnt[threadIdx.x] = 0;
}

__global__ void k_assign(const float* __restrict__ attrs, int n) {
    int b = blockIdx.x * blockDim.x + threadIdx.x;
    if (b >= n) return;
    int e = 0; float best = -1.0f;
#pragma unroll
    for (int j = 0; j < EE; j++) {
        float v = attrs[b * EE + j];
        if (v > best) { best = v; e = j; }
    }
    int pos = atomicAdd(&d_cnt[e], 1);
    d_nodeList[e * NMAX + pos] = b;
}

__global__ void k_off() {
    d_off[0] = 0; d_tileOff[0] = 0;
    for (int e = 0; e < EE; e++) {
        d_off[e + 1]     = d_off[e] + d_cnt[e];
        d_tileOff[e + 1] = d_tileOff[e] + (d_cnt[e] + 63) / 64;
    }
}

// ---------------------------------------------------------------- symmetrized U tables
__global__ void k_tables(const float* __restrict__ U3_0, const float* __restrict__ U3_1,
                         const float* __restrict__ U2_0, const float* __restrict__ U2_1) {
    int tid = threadIdx.x;
    if (tid == 0) {
        int cnt = 0;
        for (int a = 0; a < LL; a++)
            for (int b = a; b < LL; b++)
                for (int g = b; g < LL; g++) { d_m3u[cnt] = a; d_m3v[cnt] = b; d_m3w[cnt] = g; cnt++; }
        cnt = 0;
        for (int a = 0; a < LL; a++)
            for (int b = a; b < LL; b++) { d_m2u[cnt] = a; d_m2v[cnt] = b; cnt++; }
    }
    __syncthreads();

    for (int i = tid; i < M3 * 10; i += blockDim.x) {
        int m = i / 10, k = i % 10;
        int U = d_m3u[m], V = d_m3v[m], W = d_m3w[m];
        int pa[6] = {U, U, V, V, W, W}, pb[6] = {V, W, U, W, U, V}, pg[6] = {W, V, W, U, V, U};
        float s = 0.f;
        for (int p = 0; p < 6; p++) s += U3_0[((pa[p] * LL + pb[p]) * LL + pg[p]) * 10 + k];
        float dup = (U == V && V == W) ? (1.f / 6.f) : ((U == V || V == W || U == W) ? 0.5f : 1.f);
        d_T30[i] = s * dup;
    }
    for (int i = tid; i < 3 * M3 * 12; i += blockDim.x) {
        int d = i / (M3 * 12), r = i % (M3 * 12);
        int m = r / 12, k = r % 12;
        int U = d_m3u[m], V = d_m3v[m], W = d_m3w[m];
        int pa[6] = {U, U, V, V, W, W}, pb[6] = {V, W, U, W, U, V}, pg[6] = {W, V, W, U, V, U};
        float s = 0.f;
        for (int p = 0; p < 6; p++) s += U3_1[(((d * LL + pa[p]) * LL + pb[p]) * LL + pg[p]) * 12 + k];
        float dup = (U == V && V == W) ? (1.f / 6.f) : ((U == V || V == W || U == W) ? 0.5f : 1.f);
        d_T31[i] = s * dup;
    }
    for (int i = tid; i < M2 * 3; i += blockDim.x) {
        int m = i / 3, k = i % 3;
        int U = d_m2u[m], V = d_m2v[m];
        float s = U2_0[(U * LL + V) * 3 + k] + U2_0[(V * LL + U) * 3 + k];
        float dup = (U == V) ? 0.5f : 1.f;
        d_T20[i] = s * dup;
    }
    for (int i = tid; i < 3 * M2 * 4; i += blockDim.x) {
        int d = i / (M2 * 4), r = i % (M2 * 4);
        int m = r / 4, k = r % 4;
        int U = d_m2u[m], V = d_m2v[m];
        float s = U2_1[((d * LL + U) * LL + V) * 4 + k] + U2_1[((d * LL + V) * LL + U) * 4 + k];
        float dup = (U == V) ? 0.5f : 1.f;
        d_T21[i] = s * dup;
    }
}

// ---------------------------------------------------------------- coefficient build
#define MCH 32
__global__ __launch_bounds__(128) void k_coeffs2(
        const float* __restrict__ w3_0, const float* __restrict__ w2_0, const float* __restrict__ w1_0,
        const float* __restrict__ w3_1, const float* __restrict__ w2_1, const float* __restrict__ w1_1,
        const float* __restrict__ U1_0, const float* __restrict__ U1_1) {
    int e = blockIdx.y, c = threadIdx.x;
    int m0 = blockIdx.x * MCH;
    int m1 = m0 + MCH; if (m1 > MTOT) m1 = MTOT;

    float wa0[10], wa1[12], wb0[3], wb1[4];
#pragma unroll
    for (int k = 0; k < 10; k++) wa0[k] = w3_0[(e * 10 + k) * CC + c];
#pragma unroll
    for (int k = 0; k < 12; k++) wa1[k] = w3_1[(e * 12 + k) * CC + c];
#pragma unroll
    for (int k = 0; k < 3; k++)  wb0[k] = w2_0[(e * 3 + k) * CC + c];
#pragma unroll
    for (int k = 0; k < 4; k++)  wb1[k] = w2_1[(e * 4 + k) * CC + c];
    float wc0 = w1_0[e * CC + c], wc1 = w1_1[e * CC + c];

    for (int m = m0; m < m1; m++) {
        if (m < M3) {
            float s0 = 0.f;
#pragma unroll
            for (int k = 0; k < 10; k++) s0 += d_T30[m * 10 + k] * wa0[k];
            float sd[3];
#pragma unroll
            for (int d = 0; d < 3; d++) {
                float a = 0.f;
#pragma unroll
                for (int k = 0; k < 12; k++) a += d_T31[(d * M3 + m) * 12 + k] * wa1[k];
                sd[d] = a;
            }
            d_S3[(e * CC + c) * M3 + m] = make_float4(s0, sd[0], sd[1], sd[2]);
        } else if (m < M3 + M2) {
            int mm = m - M3;
            float s0 = 0.f;
#pragma unroll
            for (int k = 0; k < 3; k++) s0 += d_T20[mm * 3 + k] * wb0[k];
            float sd[3];
#pragma unroll
            for (int d = 0; d < 3; d++) {
                float a = 0.f;
#pragma unroll
                for (int k = 0; k < 4; k++) a += d_T21[(d * M2 + mm) * 4 + k] * wb1[k];
                sd[d] = a;
            }
            d_S2[(e * CC + c) * M2 + mm] = make_float4(s0, sd[0], sd[1], sd[2]);
        } else {
            int u = m - M3 - M2;
            d_S1[(e * CC + c) * M1 + u] = make_float4(
                U1_0[u] * wc0, U1_1[0 * LL + u] * wc1,
                U1_1[1 * LL + u] * wc1, U1_1[2 * LL + u] * wc1);
        }
    }
}

// ---------------------------------------------------------------- main contraction
// 4 warps/block; warp -> channel, lane -> 2 nodes (A = lane, B = lane+32) within a
// 64-node element-homogeneous tile. 4 d-slots packed as 2x f32x2; coefficients
// broadcast from shared.
__global__ __launch_bounds__(128) void k_main(const float* __restrict__ xfeat) {
    int t = blockIdx.y;
    if (t >= d_tileOff[EE]) return;
    int e = 0;
    while (t >= d_tileOff[e + 1]) e++;

    int warp = threadIdx.x >> 5, lane = threadIdx.x & 31;
    int c = blockIdx.x * 4 + warp;

    __shared__ __align__(16) float4 sh[4][MTOT];
    {
        const float4* s3 = &d_S3[(e * CC + c) * M3];
        for (int i = lane; i < M3; i += 32) sh[warp][i] = s3[i];
        const float4* s2 = &d_S2[(e * CC + c) * M2];
        for (int i = lane; i < M2; i += 32) sh[warp][M3 + i] = s2[i];
        if (lane < M1) sh[warp][M3 + M2 + lane] = d_S1[(e * CC + c) * M1 + lane];
    }
    __syncwarp();

    int cnt = d_cnt[e];
    int lt = t - d_tileOff[e];
    int niA = lt * 64 + lane, niB = niA + 32;
    bool vA = niA < cnt, vB = niB < cnt;
    int bA = d_nodeList[e * NMAX + (vA ? niA : 0)];
    int bB = d_nodeList[e * NMAX + (vB ? niB : 0)];
    int posA = d_off[e] + niA, posB = posA + 32;

    if (blockIdx.x == 0 && warp == 0) {
        if (vA) d_nodeC[posA] = bA;
        if (vB) d_nodeC[posB] = bB;
    }

    float xA[9], xB[9];
    u64 x2A[9], x2B[9];
    {
        const float* pA = xfeat + ((size_t)bA * CC + c) * LL;
        const float* pB = xfeat + ((size_t)bB * CC + c) * LL;
#pragma unroll
        for (int w = 0; w < 9; w++) {
            xA[w] = pA[w]; xB[w] = pB[w];
            SPLAT2(x2A[w], xA[w]); SPLAT2(x2B[w], xB[w]);
        }
    }

    const ulonglong2* S = reinterpret_cast<const ulonglong2*>(sh[warp]);
    u64 rA01 = 0, rA23 = 0, rB01 = 0, rB23 = 0;
    int m3 = 0, m2 = M3;
#pragma unroll
    for (int u = 0; u < 9; u++) {
#pragma unroll
        for (int v = u; v < 9; v++) {
            float pAs = xA[u] * xA[v], pBs = xB[u] * xB[v];
            u64 pA2, pB2; SPLAT2(pA2, pAs); SPLAT2(pB2, pBs);
            ulonglong2 q = S[m2++];
            u64 iA01 = q.x, iA23 = q.y, iB01 = q.x, iB23 = q.y;
#pragma unroll
            for (int w = v; w < 9; w++) {
                ulonglong2 s = S[m3++];
                FMA2(iA01, s.x, x2A[w], iA01);
                FMA2(iA23, s.y, x2A[w], iA23);
                FMA2(iB01, s.x, x2B[w], iB01);
                FMA2(iB23, s.y, x2B[w], iB23);
            }
            FMA2(rA01, pA2, iA01, rA01);
            FMA2(rA23, pA2, iA23, rA23);
            FMA2(rB01, pB2, iB01, rB01);
            FMA2(rB23, pB2, iB23, rB23);
        }
    }
#pragma unroll
    for (int u = 0; u < 9; u++) {
        ulonglong2 s = S[M3 + M2 + u];
        FMA2(rA01, s.x, x2A[u], rA01);
        FMA2(rA23, s.y, x2A[u], rA23);
        FMA2(rB01, s.x, x2B[u], rB01);
        FMA2(rB23, s.y, x2B[u], rB23);
    }

    const size_t st = (size_t)CC * NMAX;
    if (vA) {
        float f0, f1, f2, f3;
        UNPACK2(f0, f1, rA01); UNPACK2(f2, f3, rA23);
        size_t base = (size_t)c * NMAX + posA;
        d_Og[base] = f0; d_Og[st + base] = f1;
        d_Og[2 * st + base] = f2; d_Og[3 * st + base] = f3;
    }
    if (vB) {
        float f0, f1, f2, f3;
        UNPACK2(f0, f1, rB01); UNPACK2(f2, f3, rB23);
        size_t base = (size_t)c * NMAX + posB;
        d_Og[base] = f0; d_Og[st + base] = f1;
        d_Og[2 * st + base] = f2; d_Og[3 * st + base] = f3;
    }
}

// ---------------------------------------------------------------- linear + residual
#define BM 64
#define BN 64
#define BK 16
__global__ __launch_bounds__(256) void k_lin0(const float* __restrict__ lin0,
                                              const float* __restrict__ sc,
                                              float* __restrict__ out, int n) {
    __shared__ __align__(16) float As[BK][BM];
    __shared__ __align__(16) float Bs[BK][BN];
    int tid = threadIdx.x;
    int tr = tid / 16, tc = tid % 16;
    int rowBase = blockIdx.y * BM;
    int colBase = blockIdx.x * BN;

    u64 acc[4][2] = {{0, 0}, {0, 0}, {0, 0}, {0, 0}};

    for (int k0 = 0; k0 < CC; k0 += BK) {
#pragma unroll
        for (int i = 0; i < 4; i++) {
            int idx = tid + i * 256;
            int kk = idx / BM, m = idx % BM;
            int r = rowBase + m;
            As[kk][m] = (r < n) ? d_Og[(size_t)(k0 + kk) * NMAX + r] : 0.f;
        }
#pragma unroll
        for (int i = 0; i < 4; i++) {
            int idx = tid + i * 256;
            int kk = idx / BN, j = idx % BN;
            Bs[kk][j] = lin0[(k0 + kk) * CC + colBase + j];
        }
        __syncthreads();
#pragma unroll
        for (int kk = 0; kk < BK; kk++) {
            float4 av = *reinterpret_cast<const float4*>(&As[kk][tr * 4]);
            u64 a2[4];
            SPLAT2(a2[0], av.x); SPLAT2(a2[1], av.y);
            SPLAT2(a2[2], av.z); SPLAT2(a2[3], av.w);
            ulonglong2 bv = *reinterpret_cast<const ulonglong2*>(&Bs[kk][tc * 4]);
#pragma unroll
            for (int i = 0; i < 4; i++) {
                FMA2(acc[i][0], a2[i], bv.x, acc[i][0]);
                FMA2(acc[i][1], a2[i], bv.y, acc[i][1]);
            }
        }
        __syncthreads();
    }

#pragma unroll
    for (int i = 0; i < 4; i++) {
        int r = rowBase + tr * 4 + i;
        if (r >= n) continue;
        int b = d_nodeC[r];
        size_t o = (size_t)b * 512 + colBase + tc * 4;
        float4 scv = *reinterpret_cast<const float4*>(&sc[o]);
        float f0, f1, f2, f3;
        UNPACK2(f0, f1, acc[i][0]); UNPACK2(f2, f3, acc[i][1]);
        float4 ov = make_float4(f0 * INV_SQRT_C + scv.x, f1 * INV_SQRT_C + scv.y,
                                f2 * INV_SQRT_C + scv.z, f3 * INV_SQRT_C + scv.w);
        *reinterpret_cast<float4*>(&out[o]) = ov;
    }
}

// irrep-1: 3 slots share B = lin1; fused so the epilogue writes contiguous
// 12-float (j*3+d) runs into out cols [128, 512).
__global__ __launch_bounds__(256) void k_lin1(const float* __restrict__ lin1,
                                              const float* __restrict__ sc,
                                              float* __restrict__ out, int n) {
    __shared__ __align__(16) float As[3][BK][BM];
    __shared__ __align__(16) float Bs[BK][BN];
    int tid = threadIdx.x;
    int tr = tid / 16, tc = tid % 16;
    int rowBase = blockIdx.y * BM;
    int colBase = blockIdx.x * BN;

    u64 acc[3][4][2];
#pragma unroll
    for (int d = 0; d < 3; d++)
#pragma unroll
        for (int i = 0; i < 4; i++) { acc[d][i][0] = 0; acc[d][i][1] = 0; }

    const size_t st = (size_t)CC * NMAX;
    for (int k0 = 0; k0 < CC; k0 += BK) {
#pragma unroll
        for (int d = 0; d < 3; d++) {
            const float* A = d_Og + (size_t)(d + 1) * st;
#pragma unroll
            for (int i = 0; i < 4; i++) {
                int idx = tid + i * 256;
                int kk = idx / BM, m = idx % BM;
                int r = rowBase + m;
                As[d][kk][m] = (r < n) ? A[(size_t)(k0 + kk) * NMAX + r] : 0.f;
            }
        }
#pragma unroll
        for (int i = 0; i < 4; i++) {
            int idx = tid + i * 256;
            int kk = idx / BN, j = idx % BN;
            Bs[kk][j] = lin1[(k0 + kk) * CC + colBase + j];
        }
        __syncthreads();
#pragma unroll
        for (int kk = 0; kk < BK; kk++) {
            ulonglong2 bv = *reinterpret_cast<const ulonglong2*>(&Bs[kk][tc * 4]);
#pragma unroll
            for (int d = 0; d < 3; d++) {
                float4 av = *reinterpret_cast<const float4*>(&As[d][kk][tr * 4]);
                u64 a2[4];
                SPLAT2(a2[0], av.x); SPLAT2(a2[1], av.y);
                SPLAT2(a2[2], av.z); SPLAT2(a2[3], av.w);
#pragma unroll
                for (int i = 0; i < 4; i++) {
                    FMA2(acc[d][i][0], a2[i], bv.x, acc[d][i][0]);
                    FMA2(acc[d][i][1], a2[i], bv.y, acc[d][i][1]);
                }
            }
        }
        __syncthreads();
    }

#pragma unroll
    for (int i = 0; i < 4; i++) {
        int r = rowBase + tr * 4 + i;
        if (r >= n) continue;
        int b = d_nodeC[r];
        float f[12];
#pragma unroll
        for (int d = 0; d < 3; d++) {
            float l0, h0, l1, h1;
            UNPACK2(l0, h0, acc[d][i][0]);
            UNPACK2(l1, h1, acc[d][i][1]);
            f[0 * 3 + d] = l0; f[1 * 3 + d] = h0;
            f[2 * 3 + d] = l1; f[3 * 3 + d] = h1;
        }
        size_t base = (size_t)b * 512 + CC + (size_t)(colBase + tc * 4) * 3;
#pragma unroll
        for (int q = 0; q < 3; q++) {
            float4 scv = *reinterpret_cast<const float4*>(&sc[base + q * 4]);
            float4 ov = make_float4(f[q * 4 + 0] * INV_SQRT_C + scv.x,
                                    f[q * 4 + 1] * INV_SQRT_C + scv.y,
                                    f[q * 4 + 2] * INV_SQRT_C + scv.z,
                                    f[q * 4 + 3] * INV_SQRT_C + scv.w);
            *reinterpret_cast<float4*>(&out[base + q * 4]) = ov;
        }
    }
}

// ---------------------------------------------------------------- launch
extern "C" void kernel_launch(void* const* d_in, const int* in_sizes, int n_in,
                              void* d_out, int out_size) {
    const float* node_feats = (const float*)d_in[0];
    const float* node_attrs = (const float*)d_in[1];
    const float* sc         = (const float*)d_in[2];
    const float* U3_0 = (const float*)d_in[3];
    const float* U2_0 = (const float*)d_in[4];
    const float* U1_0 = (const float*)d_in[5];
    const float* w3_0 = (const float*)d_in[6];
    const float* w2_0 = (const float*)d_in[7];
    const float* w1_0 = (const float*)d_in[8];
    const float* U3_1 = (const float*)d_in[9];
    const float* U2_1 = (const float*)d_in[10];
    const float* U1_1 = (const float*)d_in[11];
    const float* w3_1 = (const float*)d_in[12];
    const float* w2_1 = (const float*)d_in[13];
    const float* w1_1 = (const float*)d_in[14];
    const float* lin_w0 = (const float*)d_in[15];
    const float* lin_w1 = (const float*)d_in[16];

    int n = in_sizes[0] / (CC * LL);

    k_init<<<1, 32>>>();
    k_assign<<<(n + 255) / 256, 256>>>(node_attrs, n);
    k_off<<<1, 1>>>();
    k_tables<<<1, 256>>>(U3_0, U3_1, U2_0, U2_1);

    dim3 gc((MTOT + MCH - 1) / MCH, EE);
    k_coeffs2<<<gc, 128>>>(w3_0, w2_0, w1_0, w3_1, w2_1, w1_1, U1_0, U1_1);

    int maxT = (n + 63) / 64 + EE;
    k_main<<<dim3(CC / 4, maxT), 128>>>(node_feats);

    dim3 gl(CC / BN, (n + BM - 1) / BM);
    k_lin0<<<gl, 256>>>(lin_w0, sc, (float*)d_out, n);
    k_lin1<<<gl, 256>>>(lin_w1, sc, (float*)d_out, n);
}

// round 6
// speedup vs baseline: 1.7373x; 1.2657x over previous
#include <cuda_runtime.h>
#include <cstdint>

#define CC 128
#define LL 9
#define EE 5
#define NMAX 10000
#define M3 165
#define M2 45
#define M1 9
#define MTOT (M3 + M2 + M1)   // 219
#define INV_SQRT_C 0.08838834764831845f

typedef unsigned long long u64;

// packed f32x2 helpers (SASS FFMA2 — only via PTX)
#define FMA2(d, a, b, c) asm("fma.rn.f32x2 %0, %1, %2, %3;" : "=l"(d) : "l"(a), "l"(b), "l"(c))
#define SPLAT2(d, s)     asm("mov.b64 %0, {%1, %1};" : "=l"(d) : "r"(__float_as_uint(s)))
#define UNPACK2(lo, hi, v) do { unsigned _lo, _hi; \
    asm("mov.b64 {%0, %1}, %2;" : "=r"(_lo), "=r"(_hi) : "l"(v)); \
    lo = __uint_as_float(_lo); hi = __uint_as_float(_hi); } while (0)

static __device__ int    d_cnt[EE];
static __device__ int    d_off[EE + 1];       // exact prefix of counts
static __device__ int    d_tileOff[EE + 1];   // prefix of 64-node tiles
static __device__ int    d_nodeList[EE * NMAX];
static __device__ int    d_nodeC[NMAX];       // compact pos -> node id
static __device__ float4 d_S3[EE * CC * M3];
static __device__ float4 d_S2[EE * CC * M2];
static __device__ float4 d_S1[EE * CC * M1];
static __device__ float  d_Og[4 * (size_t)CC * NMAX];  // [slot][c][pos]
// symmetrized U tables
static __device__ int   d_m3u[M3], d_m3v[M3], d_m3w[M3];
static __device__ int   d_m2u[M2], d_m2v[M2];
static __device__ float d_T30[M3 * 10];
static __device__ float d_T31[3 * M3 * 12];
static __device__ float d_T20[M2 * 3];
static __device__ float d_T21[3 * M2 * 4];

// ---------------------------------------------------------------- bucketing
__global__ void k_init() {
    if (threadIdx.x < EE) d_cnt[threadIdx.x] = 0;
}

__global__ void k_assign(const float* __restrict__ attrs, int n) {
    int b = blockIdx.x * blockDim.x + threadIdx.x;
    if (b >= n) return;
    int e = 0; float best = -1.0f;
#pragma unroll
    for (int j = 0; j < EE; j++) {
        float v = attrs[b * EE + j];
        if (v > best) { best = v; e = j; }
    }
    int pos = atomicAdd(&d_cnt[e], 1);
    d_nodeList[e * NMAX + pos] = b;
}

__global__ void k_off() {
    d_off[0] = 0; d_tileOff[0] = 0;
    for (int e = 0; e < EE; e++) {
        d_off[e + 1]     = d_off[e] + d_cnt[e];
        d_tileOff[e + 1] = d_tileOff[e] + (d_cnt[e] + 63) / 64;
    }
}

// ---------------------------------------------------------------- monomial index maps
// m -> (U<=V<=W) for cubic, m -> (U<=V) for quadratic. Per-thread arithmetic decode.
__global__ void k_idx() {
    int m = threadIdx.x;
    if (m < M3) {
        int cnt = 0, U = 0, V = 0, W = 0;
        for (int a = 0; a < LL; a++) {
            int blk = (LL - a) * (LL - a + 1) / 2;   // # of (b,g) with a<=b<=g
            if (m < cnt + blk) {
                U = a;
                int r = m - cnt;
                int c2 = 0;
                for (int b = a; b < LL; b++) {
                    int run = LL - b;
                    if (r < c2 + run) { V = b; W = b + (r - c2); break; }
                    c2 += run;
                }
                break;
            }
            cnt += blk;
        }
        d_m3u[m] = U; d_m3v[m] = V; d_m3w[m] = W;
    }
    if (m < M2) {
        int cnt = 0, U = 0, V = 0;
        for (int a = 0; a < LL; a++) {
            int run = LL - a;
            if (m < cnt + run) { U = a; V = a + (m - cnt); break; }
            cnt += run;
        }
        d_m2u[m] = U; d_m2v[m] = V;
    }
}

// ---------------------------------------------------------------- symmetrized U tables
// grid-stride over all 8265 table elements: T3x = dup * sum_perm U3x, etc.
#define TW3A (M3 * 10)
#define TW3B (3 * M3 * 12)
#define TW2A (M2 * 3)
#define TW2B (3 * M2 * 4)
#define TWTOT (TW3A + TW3B + TW2A + TW2B)
__global__ __launch_bounds__(256) void k_tables(const float* __restrict__ U3_0,
                                                const float* __restrict__ U3_1,
                                                const float* __restrict__ U2_0,
                                                const float* __restrict__ U2_1) {
    int i = blockIdx.x * blockDim.x + threadIdx.x;
    if (i >= TWTOT) return;

    if (i < TW3A) {
        int m = i / 10, k = i % 10;
        int U = d_m3u[m], V = d_m3v[m], W = d_m3w[m];
        int pa[6] = {U, U, V, V, W, W}, pb[6] = {V, W, U, W, U, V}, pg[6] = {W, V, W, U, V, U};
        float s = 0.f;
#pragma unroll
        for (int p = 0; p < 6; p++) s += U3_0[((pa[p] * LL + pb[p]) * LL + pg[p]) * 10 + k];
        float dup = (U == V && V == W) ? (1.f / 6.f) : ((U == V || V == W || U == W) ? 0.5f : 1.f);
        d_T30[i] = s * dup;
    } else if (i < TW3A + TW3B) {
        int j = i - TW3A;
        int d = j / (M3 * 12), r = j % (M3 * 12);
        int m = r / 12, k = r % 12;
        int U = d_m3u[m], V = d_m3v[m], W = d_m3w[m];
        int pa[6] = {U, U, V, V, W, W}, pb[6] = {V, W, U, W, U, V}, pg[6] = {W, V, W, U, V, U};
        float s = 0.f;
#pragma unroll
        for (int p = 0; p < 6; p++) s += U3_1[(((d * LL + pa[p]) * LL + pb[p]) * LL + pg[p]) * 12 + k];
        float dup = (U == V && V == W) ? (1.f / 6.f) : ((U == V || V == W || U == W) ? 0.5f : 1.f);
        d_T31[j] = s * dup;
    } else if (i < TW3A + TW3B + TW2A) {
        int j = i - TW3A - TW3B;
        int m = j / 3, k = j % 3;
        int U = d_m2u[m], V = d_m2v[m];
        float s = U2_0[(U * LL + V) * 3 + k] + U2_0[(V * LL + U) * 3 + k];
        d_T20[j] = s * ((U == V) ? 0.5f : 1.f);
    } else {
        int j = i - TW3A - TW3B - TW2A;
        int d = j / (M2 * 4), r = j % (M2 * 4);
        int m = r / 4, k = r % 4;
        int U = d_m2u[m], V = d_m2v[m];
        float s = U2_1[((d * LL + U) * LL + V) * 4 + k] + U2_1[((d * LL + V) * LL + U) * 4 + k];
        d_T21[j] = s * ((U == V) ? 0.5f : 1.f);
    }
}

// ---------------------------------------------------------------- coefficient build
#define MCH 16
__global__ __launch_bounds__(128) void k_coeffs2(
        const float* __restrict__ w3_0, const float* __restrict__ w2_0, const float* __restrict__ w1_0,
        const float* __restrict__ w3_1, const float* __restrict__ w2_1, const float* __restrict__ w1_1,
        const float* __restrict__ U1_0, const float* __restrict__ U1_1) {
    int e = blockIdx.y, c = threadIdx.x;
    int m0 = blockIdx.x * MCH;
    int m1 = m0 + MCH; if (m1 > MTOT) m1 = MTOT;

    float wa0[10], wa1[12], wb0[3], wb1[4];
#pragma unroll
    for (int k = 0; k < 10; k++) wa0[k] = w3_0[(e * 10 + k) * CC + c];
#pragma unroll
    for (int k = 0; k < 12; k++) wa1[k] = w3_1[(e * 12 + k) * CC + c];
#pragma unroll
    for (int k = 0; k < 3; k++)  wb0[k] = w2_0[(e * 3 + k) * CC + c];
#pragma unroll
    for (int k = 0; k < 4; k++)  wb1[k] = w2_1[(e * 4 + k) * CC + c];
    float wc0 = w1_0[e * CC + c], wc1 = w1_1[e * CC + c];

    for (int m = m0; m < m1; m++) {
        if (m < M3) {
            float s0 = 0.f;
#pragma unroll
            for (int k = 0; k < 10; k++) s0 += d_T30[m * 10 + k] * wa0[k];
            float sd[3];
#pragma unroll
            for (int d = 0; d < 3; d++) {
                float a = 0.f;
#pragma unroll
                for (int k = 0; k < 12; k++) a += d_T31[(d * M3 + m) * 12 + k] * wa1[k];
                sd[d] = a;
            }
            d_S3[(e * CC + c) * M3 + m] = make_float4(s0, sd[0], sd[1], sd[2]);
        } else if (m < M3 + M2) {
            int mm = m - M3;
            float s0 = 0.f;
#pragma unroll
            for (int k = 0; k < 3; k++) s0 += d_T20[mm * 3 + k] * wb0[k];
            float sd[3];
#pragma unroll
            for (int d = 0; d < 3; d++) {
                float a = 0.f;
#pragma unroll
                for (int k = 0; k < 4; k++) a += d_T21[(d * M2 + mm) * 4 + k] * wb1[k];
                sd[d] = a;
            }
            d_S2[(e * CC + c) * M2 + mm] = make_float4(s0, sd[0], sd[1], sd[2]);
        } else {
            int u = m - M3 - M2;
            d_S1[(e * CC + c) * M1 + u] = make_float4(
                U1_0[u] * wc0, U1_1[0 * LL + u] * wc1,
                U1_1[1 * LL + u] * wc1, U1_1[2 * LL + u] * wc1);
        }
    }
}

// ---------------------------------------------------------------- main contraction
// 4 warps/block; warp -> channel, lane -> 2 nodes (A = lane, B = lane+32) within a
// 64-node element-homogeneous tile. 4 d-slots packed as 2x f32x2; coefficients
// broadcast from shared.
__global__ __launch_bounds__(128) void k_main(const float* __restrict__ xfeat) {
    int t = blockIdx.y;
    if (t >= d_tileOff[EE]) return;
    int e = 0;
    while (t >= d_tileOff[e + 1]) e++;

    int warp = threadIdx.x >> 5, lane = threadIdx.x & 31;
    int c = blockIdx.x * 4 + warp;

    __shared__ __align__(16) float4 sh[4][MTOT];
    {
        const float4* s3 = &d_S3[(e * CC + c) * M3];
        for (int i = lane; i < M3; i += 32) sh[warp][i] = s3[i];
        const float4* s2 = &d_S2[(e * CC + c) * M2];
        for (int i = lane; i < M2; i += 32) sh[warp][M3 + i] = s2[i];
        if (lane < M1) sh[warp][M3 + M2 + lane] = d_S1[(e * CC + c) * M1 + lane];
    }
    __syncwarp();

    int cnt = d_cnt[e];
    int lt = t - d_tileOff[e];
    int niA = lt * 64 + lane, niB = niA + 32;
    bool vA = niA < cnt, vB = niB < cnt;
    int bA = d_nodeList[e * NMAX + (vA ? niA : 0)];
    int bB = d_nodeList[e * NMAX + (vB ? niB : 0)];
    int posA = d_off[e] + niA, posB = posA + 32;

    if (blockIdx.x == 0 && warp == 0) {
        if (vA) d_nodeC[posA] = bA;
        if (vB) d_nodeC[posB] = bB;
    }

    float xA[9], xB[9];
    u64 x2A[9], x2B[9];
    {
        const float* pA = xfeat + ((size_t)bA * CC + c) * LL;
        const float* pB = xfeat + ((size_t)bB * CC + c) * LL;
#pragma unroll
        for (int w = 0; w < 9; w++) {
            xA[w] = pA[w]; xB[w] = pB[w];
            SPLAT2(x2A[w], xA[w]); SPLAT2(x2B[w], xB[w]);
        }
    }

    const ulonglong2* S = reinterpret_cast<const ulonglong2*>(sh[warp]);
    u64 rA01 = 0, rA23 = 0, rB01 = 0, rB23 = 0;
    int m3 = 0, m2 = M3;
#pragma unroll
    for (int u = 0; u < 9; u++) {
#pragma unroll
        for (int v = u; v < 9; v++) {
            float pAs = xA[u] * xA[v], pBs = xB[u] * xB[v];
            u64 pA2, pB2; SPLAT2(pA2, pAs); SPLAT2(pB2, pBs);
            ulonglong2 q = S[m2++];
            u64 iA01 = q.x, iA23 = q.y, iB01 = q.x, iB23 = q.y;
#pragma unroll
            for (int w = v; w < 9; w++) {
                ulonglong2 s = S[m3++];
                FMA2(iA01, s.x, x2A[w], iA01);
                FMA2(iA23, s.y, x2A[w], iA23);
                FMA2(iB01, s.x, x2B[w], iB01);
                FMA2(iB23, s.y, x2B[w], iB23);
            }
            FMA2(rA01, pA2, iA01, rA01);
            FMA2(rA23, pA2, iA23, rA23);
            FMA2(rB01, pB2, iB01, rB01);
            FMA2(rB23, pB2, iB23, rB23);
        }
    }
#pragma unroll
    for (int u = 0; u < 9; u++) {
        ulonglong2 s = S[M3 + M2 + u];
        FMA2(rA01, s.x, x2A[u], rA01);
        FMA2(rA23, s.y, x2A[u], rA23);
        FMA2(rB01, s.x, x2B[u], rB01);
        FMA2(rB23, s.y, x2B[u], rB23);
    }

    const size_t st = (size_t)CC * NMAX;
    if (vA) {
        float f0, f1, f2, f3;
        UNPACK2(f0, f1, rA01); UNPACK2(f2, f3, rA23);
        size_t base = (size_t)c * NMAX + posA;
        d_Og[base] = f0; d_Og[st + base] = f1;
        d_Og[2 * st + base] = f2; d_Og[3 * st + base] = f3;
    }
    if (vB) {
        float f0, f1, f2, f3;
        UNPACK2(f0, f1, rB01); UNPACK2(f2, f3, rB23);
        size_t base = (size_t)c * NMAX + posB;
        d_Og[base] = f0; d_Og[st + base] = f1;
        d_Og[2 * st + base] = f2; d_Og[3 * st + base] = f3;
    }
}

// ---------------------------------------------------------------- linear + residual
#define BM 64
#define BN 64
#define BK 16
__global__ __launch_bounds__(256) void k_lin0(const float* __restrict__ lin0,
                                              const float* __restrict__ sc,
                                              float* __restrict__ out, int n) {
    __shared__ __align__(16) float As[BK][BM];
    __shared__ __align__(16) float Bs[BK][BN];
    int tid = threadIdx.x;
    int tr = tid / 16, tc = tid % 16;
    int rowBase = blockIdx.y * BM;
    int colBase = blockIdx.x * BN;

    u64 acc[4][2] = {{0, 0}, {0, 0}, {0, 0}, {0, 0}};

    for (int k0 = 0; k0 < CC; k0 += BK) {
#pragma unroll
        for (int i = 0; i < 4; i++) {
            int idx = tid + i * 256;
            int kk = idx / BM, m = idx % BM;
            int r = rowBase + m;
            As[kk][m] = (r < n) ? d_Og[(size_t)(k0 + kk) * NMAX + r] : 0.f;
        }
#pragma unroll
        for (int i = 0; i < 4; i++) {
            int idx = tid + i * 256;
            int kk = idx / BN, j = idx % BN;
            Bs[kk][j] = lin0[(k0 + kk) * CC + colBase + j];
        }
        __syncthreads();
#pragma unroll
        for (int kk = 0; kk < BK; kk++) {
            float4 av = *reinterpret_cast<const float4*>(&As[kk][tr * 4]);
            u64 a2[4];
            SPLAT2(a2[0], av.x); SPLAT2(a2[1], av.y);
            SPLAT2(a2[2], av.z); SPLAT2(a2[3], av.w);
            ulonglong2 bv = *reinterpret_cast<const ulonglong2*>(&Bs[kk][tc * 4]);
#pragma unroll
            for (int i = 0; i < 4; i++) {
                FMA2(acc[i][0], a2[i], bv.x, acc[i][0]);
                FMA2(acc[i][1], a2[i], bv.y, acc[i][1]);
            }
        }
        __syncthreads();
    }

#pragma unroll
    for (int i = 0; i < 4; i++) {
        int r = rowBase + tr * 4 + i;
        if (r >= n) continue;
        int b = d_nodeC[r];
        size_t o = (size_t)b * 512 + colBase + tc * 4;
        float4 scv = *reinterpret_cast<const float4*>(&sc[o]);
        float f0, f1, f2, f3;
        UNPACK2(f0, f1, acc[i][0]); UNPACK2(f2, f3, acc[i][1]);
        float4 ov = make_float4(f0 * INV_SQRT_C + scv.x, f1 * INV_SQRT_C + scv.y,
                                f2 * INV_SQRT_C + scv.z, f3 * INV_SQRT_C + scv.w);
        *reinterpret_cast<float4*>(&out[o]) = ov;
    }
}

// irrep-1: 3 slots share B = lin1; fused so the epilogue writes contiguous
// 12-float (j*3+d) runs into out cols [128, 512).
__global__ __launch_bounds__(256) void k_lin1(const float* __restrict__ lin1,
                                              const float* __restrict__ sc,
                                              float* __restrict__ out, int n) {
    __shared__ __align__(16) float As[3][BK][BM];
    __shared__ __align__(16) float Bs[BK][BN];
    int tid = threadIdx.x;
    int tr = tid / 16, tc = tid % 16;
    int rowBase = blockIdx.y * BM;
    int colBase = blockIdx.x * BN;

    u64 acc[3][4][2];
#pragma unroll
    for (int d = 0; d < 3; d++)
#pragma unroll
        for (int i = 0; i < 4; i++) { acc[d][i][0] = 0; acc[d][i][1] = 0; }

    const size_t st = (size_t)CC * NMAX;
    for (int k0 = 0; k0 < CC; k0 += BK) {
#pragma unroll
        for (int d = 0; d < 3; d++) {
            const float* A = d_Og + (size_t)(d + 1) * st;
#pragma unroll
            for (int i = 0; i < 4; i++) {
                int idx = tid + i * 256;
                int kk = idx / BM, m = idx % BM;
                int r = rowBase + m;
                As[d][kk][m] = (r < n) ? A[(size_t)(k0 + kk) * NMAX + r] : 0.f;
            }
        }
#pragma unroll
        for (int i = 0; i < 4; i++) {
            int idx = tid + i * 256;
            int kk = idx / BN, j = idx % BN;
            Bs[kk][j] = lin1[(k0 + kk) * CC + colBase + j];
        }
        __syncthreads();
#pragma unroll
        for (int kk = 0; kk < BK; kk++) {
            ulonglong2 bv = *reinterpret_cast<const ulonglong2*>(&Bs[kk][tc * 4]);
#pragma unroll
            for (int d = 0; d < 3; d++) {
                float4 av = *reinterpret_cast<const float4*>(&As[d][kk][tr * 4]);
                u64 a2[4];
                SPLAT2(a2[0], av.x); SPLAT2(a2[1], av.y);
                SPLAT2(a2[2], av.z); SPLAT2(a2[3], av.w);
#pragma unroll
                for (int i = 0; i < 4; i++) {
                    FMA2(acc[d][i][0], a2[i], bv.x, acc[d][i][0]);
                    FMA2(acc[d][i][1], a2[i], bv.y, acc[d][i][1]);
                }
            }
        }
        __syncthreads();
    }

#pragma unroll
    for (int i = 0; i < 4; i++) {
        int r = rowBase + tr * 4 + i;
        if (r >= n) continue;
        int b = d_nodeC[r];
        float f[12];
#pragma unroll
        for (int d = 0; d < 3; d++) {
            float l0, h0, l1, h1;
            UNPACK2(l0, h0, acc[d][i][0]);
            UNPACK2(l1, h1, acc[d][i][1]);
            f[0 * 3 + d] = l0; f[1 * 3 + d] = h0;
            f[2 * 3 + d] = l1; f[3 * 3 + d] = h1;
        }
        size_t base = (size_t)b * 512 + CC + (size_t)(colBase + tc * 4) * 3;
#pragma unroll
        for (int q = 0; q < 3; q++) {
            float4 scv = *reinterpret_cast<const float4*>(&sc[base + q * 4]);
            float4 ov = make_float4(f[q * 4 + 0] * INV_SQRT_C + scv.x,
                                    f[q * 4 + 1] * INV_SQRT_C + scv.y,
                                    f[q * 4 + 2] * INV_SQRT_C + scv.z,
                                    f[q * 4 + 3] * INV_SQRT_C + scv.w);
            *reinterpret_cast<float4*>(&out[base + q * 4]) = ov;
        }
    }
}

// ---------------------------------------------------------------- launch
extern "C" void kernel_launch(void* const* d_in, const int* in_sizes, int n_in,
                              void* d_out, int out_size) {
    const float* node_feats = (const float*)d_in[0];
    const float* node_attrs = (const float*)d_in[1];
    const float* sc         = (const float*)d_in[2];
    const float* U3_0 = (const float*)d_in[3];
    const float* U2_0 = (const float*)d_in[4];
    const float* U1_0 = (const float*)d_in[5];
    const float* w3_0 = (const float*)d_in[6];
    const float* w2_0 = (const float*)d_in[7];
    const float* w1_0 = (const float*)d_in[8];
    const float* U3_1 = (const float*)d_in[9];
    const float* U2_1 = (const float*)d_in[10];
    const float* U1_1 = (const float*)d_in[11];
    const float* w3_1 = (const float*)d_in[12];
    const float* w2_1 = (const float*)d_in[13];
    const float* w1_1 = (const float*)d_in[14];
    const float* lin_w0 = (const float*)d_in[15];
    const float* lin_w1 = (const float*)d_in[16];

    int n = in_sizes[0] / (CC * LL);

    k_init<<<1, 32>>>();
    k_assign<<<(n + 255) / 256, 256>>>(node_attrs, n);
    k_off<<<1, 1>>>();
    k_idx<<<1, 256>>>();
    k_tables<<<(TWTOT + 255) / 256, 256>>>(U3_0, U3_1, U2_0, U2_1);

    dim3 gc((MTOT + MCH - 1) / MCH, EE);
    k_coeffs2<<<gc, 128>>>(w3_0, w2_0, w1_0, w3_1, w2_1, w1_1, U1_0, U1_1);

    int maxT = (n + 63) / 64 + EE;
    k_main<<<dim3(CC / 4, maxT), 128>>>(node_feats);

    dim3 gl(CC / BN, (n + BM - 1) / BM);
    k_lin0<<<gl, 256>>>(lin_w0, sc, (float*)d_out, n);
    k_lin1<<<gl, 256>>>(lin_w1, sc, (float*)d_out, n);
}

// round 10
// speedup vs baseline: 1.9900x; 1.1454x over previous
#include <cuda_runtime.h>
#include <cstdint>

#define CC 128
#define LL 9
#define EE 5
#define NMAX 10000
#define M3 165
#define M2 45
#define M1 9
#define MTOT (M3 + M2 + M1)   // 219
#define INV_SQRT_C 0.08838834764831845f

typedef unsigned long long u64;

// packed f32x2 helpers (SASS FFMA2 — only via PTX)
#define FMA2(d, a, b, c) asm("fma.rn.f32x2 %0, %1, %2, %3;" : "=l"(d) : "l"(a), "l"(b), "l"(c))
#define SPLAT2(d, s)     asm("mov.b64 %0, {%1, %1};" : "=l"(d) : "r"(__float_as_uint(s)))
#define UNPACK2(lo, hi, v) do { unsigned _lo, _hi; \
    asm("mov.b64 {%0, %1}, %2;" : "=r"(_lo), "=r"(_hi) : "l"(v)); \
    lo = __uint_as_float(_lo); hi = __uint_as_float(_hi); } while (0)

static __device__ int    d_cnt[EE];
static __device__ int    d_off[EE + 1];       // exact prefix of counts
static __device__ int    d_tileOff[EE + 1];   // prefix of 64-node tiles
static __device__ int    d_nodeList[EE * NMAX];
static __device__ int    d_nodeC[NMAX];       // compact pos -> node id
static __device__ float4 d_S3[EE * CC * M3];
static __device__ float4 d_S2[EE * CC * M2];
static __device__ float4 d_S1[EE * CC * M1];
static __device__ float  d_Og[4 * (size_t)CC * NMAX];  // [slot][c][pos]

// ---------------------------------------------------------------- bucketing
__global__ void k_init() {
    if (threadIdx.x < EE) d_cnt[threadIdx.x] = 0;
}

__global__ void k_assign(const float* __restrict__ attrs, int n) {
    int b = blockIdx.x * blockDim.x + threadIdx.x;
    if (b >= n) return;
    int e = 0; float best = -1.0f;
#pragma unroll
    for (int j = 0; j < EE; j++) {
        float v = attrs[b * EE + j];
        if (v > best) { best = v; e = j; }
    }
    int pos = atomicAdd(&d_cnt[e], 1);
    d_nodeList[e * NMAX + pos] = b;
}

// ---------------------------------------------------------------- monomial decode
__device__ __forceinline__ void decode3(int m, int& U, int& V, int& W) {
    int cnt = 0;
    U = V = W = 0;
    for (int a = 0; a < LL; a++) {
        int blk = (LL - a) * (LL - a + 1) / 2;
        if (m < cnt + blk) {
            U = a;
            int r = m - cnt, c2 = 0;
            for (int b = a; b < LL; b++) {
                int run = LL - b;
                if (r < c2 + run) { V = b; W = b + (r - c2); return; }
                c2 += run;
            }
            return;
        }
        cnt += blk;
    }
}
__device__ __forceinline__ void decode2(int m, int& U, int& V) {
    int cnt = 0;
    U = V = 0;
    for (int a = 0; a < LL; a++) {
        int run = LL - a;
        if (m < cnt + run) { U = a; V = a + (m - cnt); return; }
        cnt += run;
    }
}

// ---------------------------------------------------------------- coefficient build
// Fuses: prefix-scan (block 0,0), symmetrized-U table build (per m-chunk, in shared),
// and the S = T·w contraction. Grid: (ceil(MTOT/MCH), EE), 128 threads.
#define MCH 16
__global__ __launch_bounds__(128) void k_coeffs(
        const float* __restrict__ U3_0, const float* __restrict__ U2_0, const float* __restrict__ U1_0,
        const float* __restrict__ w3_0, const float* __restrict__ w2_0, const float* __restrict__ w1_0,
        const float* __restrict__ U3_1, const float* __restrict__ U2_1, const float* __restrict__ U1_1,
        const float* __restrict__ w3_1, const float* __restrict__ w2_1, const float* __restrict__ w1_1) {

    // folded k_off: prefix scan (d_cnt is consumed read-only; k_init re-zeroes each run)
    if (blockIdx.x == 0 && blockIdx.y == 0 && threadIdx.x == 0) {
        int off = 0, toff = 0;
        d_off[0] = 0; d_tileOff[0] = 0;
#pragma unroll
        for (int e = 0; e < EE; e++) {
            int cnt = d_cnt[e];
            off += cnt; toff += (cnt + 63) / 64;
            d_off[e + 1] = off; d_tileOff[e + 1] = toff;
        }
    }

    int e = blockIdx.y, c = threadIdx.x;
    int m0 = blockIdx.x * MCH;
    int m1 = m0 + MCH; if (m1 > MTOT) m1 = MTOT;

    // stage symmetrized tables for this m-chunk:
    // shA[mi][k] : cubic T30 (k<10) or quadratic T20 (k<3)
    // shB[d][mi][k] : cubic T31 (k<12) or quadratic T21 (k<4)
    __shared__ float shA[MCH][10];
    __shared__ float shB[3][MCH][12];

    for (int i = threadIdx.x; i < MCH * 10; i += 128) {
        int mi = i / 10, k = i % 10;
        int m = m0 + mi;
        float val = 0.f;
        if (m < M3) {
            int U, V, W; decode3(m, U, V, W);
            int pa[6] = {U, U, V, V, W, W}, pb[6] = {V, W, U, W, U, V}, pg[6] = {W, V, W, U, V, U};
            float s = 0.f;
#pragma unroll
            for (int p = 0; p < 6; p++) s += U3_0[((pa[p] * LL + pb[p]) * LL + pg[p]) * 10 + k];
            float dup = (U == V && V == W) ? (1.f / 6.f) : ((U == V || V == W || U == W) ? 0.5f : 1.f);
            val = s * dup;
        } else if (m < M3 + M2 && k < 3) {
            int U, V; decode2(m - M3, U, V);
            float s = U2_0[(U * LL + V) * 3 + k] + U2_0[(V * LL + U) * 3 + k];
            val = s * ((U == V) ? 0.5f : 1.f);
        }
        shA[mi][k] = val;
    }
    for (int i = threadIdx.x; i < 3 * MCH * 12; i += 128) {
        int d = i / (MCH * 12), r = i % (MCH * 12);
        int mi = r / 12, k = r % 12;
        int m = m0 + mi;
        float val = 0.f;
        if (m < M3) {
            int U, V, W; decode3(m, U, V, W);
            int pa[6] = {U, U, V, V, W, W}, pb[6] = {V, W, U, W, U, V}, pg[6] = {W, V, W, U, V, U};
            float s = 0.f;
#pragma unroll
            for (int p = 0; p < 6; p++) s += U3_1[(((d * LL + pa[p]) * LL + pb[p]) * LL + pg[p]) * 12 + k];
            float dup = (U == V && V == W) ? (1.f / 6.f) : ((U == V || V == W || U == W) ? 0.5f : 1.f);
            val = s * dup;
        } else if (m < M3 + M2 && k < 4) {
            int U, V; decode2(m - M3, U, V);
            float s = U2_1[((d * LL + U) * LL + V) * 4 + k] + U2_1[((d * LL + V) * LL + U) * 4 + k];
            val = s * ((U == V) ? 0.5f : 1.f);
        }
        shB[d][mi][k] = val;
    }
    __syncthreads();

    // per-channel weights
    float wa0[10], wa1[12], wb0[3], wb1[4];
#pragma unroll
    for (int k = 0; k < 10; k++) wa0[k] = w3_0[(e * 10 + k) * CC + c];
#pragma unroll
    for (int k = 0; k < 12; k++) wa1[k] = w3_1[(e * 12 + k) * CC + c];
#pragma unroll
    for (int k = 0; k < 3; k++)  wb0[k] = w2_0[(e * 3 + k) * CC + c];
#pragma unroll
    for (int k = 0; k < 4; k++)  wb1[k] = w2_1[(e * 4 + k) * CC + c];
    float wc0 = w1_0[e * CC + c], wc1 = w1_1[e * CC + c];

    for (int m = m0; m < m1; m++) {
        int mi = m - m0;
        if (m < M3) {
            float s0 = 0.f;
#pragma unroll
            for (int k = 0; k < 10; k++) s0 += shA[mi][k] * wa0[k];
            float sd[3];
#pragma unroll
            for (int d = 0; d < 3; d++) {
                float a = 0.f;
#pragma unroll
                for (int k = 0; k < 12; k++) a += shB[d][mi][k] * wa1[k];
                sd[d] = a;
            }
            d_S3[(e * CC + c) * M3 + m] = make_float4(s0, sd[0], sd[1], sd[2]);
        } else if (m < M3 + M2) {
            int mm = m - M3;
            float s0 = 0.f;
#pragma unroll
            for (int k = 0; k < 3; k++) s0 += shA[mi][k] * wb0[k];
            float sd[3];
#pragma unroll
            for (int d = 0; d < 3; d++) {
                float a = 0.f;
#pragma unroll
                for (int k = 0; k < 4; k++) a += shB[d][mi][k] * wb1[k];
                sd[d] = a;
            }
            d_S2[(e * CC + c) * M2 + mm] = make_float4(s0, sd[0], sd[1], sd[2]);
        } else {
            int u = m - M3 - M2;
            d_S1[(e * CC + c) * M1 + u] = make_float4(
                U1_0[u] * wc0, U1_1[0 * LL + u] * wc1,
                U1_1[1 * LL + u] * wc1, U1_1[2 * LL + u] * wc1);
        }
    }
}

// ---------------------------------------------------------------- main contraction
// 4 warps/block; warp -> channel, lane -> 2 nodes (A = lane, B = lane+32) within a
// 64-node element-homogeneous tile. 4 d-slots packed as 2x f32x2; coefficients
// broadcast from shared.
__global__ __launch_bounds__(128) void k_main(const float* __restrict__ xfeat) {
    int t = blockIdx.y;
    if (t >= d_tileOff[EE]) return;
    int e = 0;
    while (t >= d_tileOff[e + 1]) e++;

    int warp = threadIdx.x >> 5, lane = threadIdx.x & 31;
    int c = blockIdx.x * 4 + warp;

    __shared__ __align__(16) float4 sh[4][MTOT];
    {
        const float4* s3 = &d_S3[(e * CC + c) * M3];
        for (int i = lane; i < M3; i += 32) sh[warp][i] = s3[i];
        const float4* s2 = &d_S2[(e * CC + c) * M2];
        for (int i = lane; i < M2; i += 32) sh[warp][M3 + i] = s2[i];
        if (lane < M1) sh[warp][M3 + M2 + lane] = d_S1[(e * CC + c) * M1 + lane];
    }
    __syncwarp();

    int cnt = d_off[e + 1] - d_off[e];
    int lt = t - d_tileOff[e];
    int niA = lt * 64 + lane, niB = niA + 32;
    bool vA = niA < cnt, vB = niB < cnt;
    int bA = d_nodeList[e * NMAX + (vA ? niA : 0)];
    int bB = d_nodeList[e * NMAX + (vB ? niB : 0)];
    int posA = d_off[e] + niA, posB = posA + 32;

    if (blockIdx.x == 0 && warp == 0) {
        if (vA) d_nodeC[posA] = bA;
        if (vB) d_nodeC[posB] = bB;
    }

    float xA[9], xB[9];
    u64 x2A[9], x2B[9];
    {
        const float* pA = xfeat + ((size_t)bA * CC + c) * LL;
        const float* pB = xfeat + ((size_t)bB * CC + c) * LL;
#pragma unroll
        for (int w = 0; w < 9; w++) {
            xA[w] = pA[w]; xB[w] = pB[w];
            SPLAT2(x2A[w], xA[w]); SPLAT2(x2B[w], xB[w]);
        }
    }

    const ulonglong2* S = reinterpret_cast<const ulonglong2*>(sh[warp]);
    u64 rA01 = 0, rA23 = 0, rB01 = 0, rB23 = 0;
    int m3 = 0, m2 = M3;
#pragma unroll
    for (int u = 0; u < 9; u++) {
#pragma unroll
        for (int v = u; v < 9; v++) {
            float pAs = xA[u] * xA[v], pBs = xB[u] * xB[v];
            u64 pA2, pB2; SPLAT2(pA2, pAs); SPLAT2(pB2, pBs);
            ulonglong2 q = S[m2++];
            u64 iA01 = q.x, iA23 = q.y, iB01 = q.x, iB23 = q.y;
#pragma unroll
            for (int w = v; w < 9; w++) {
                ulonglong2 s = S[m3++];
                FMA2(iA01, s.x, x2A[w], iA01);
                FMA2(iA23, s.y, x2A[w], iA23);
                FMA2(iB01, s.x, x2B[w], iB01);
                FMA2(iB23, s.y, x2B[w], iB23);
            }
            FMA2(rA01, pA2, iA01, rA01);
            FMA2(rA23, pA2, iA23, rA23);
            FMA2(rB01, pB2, iB01, rB01);
            FMA2(rB23, pB2, iB23, rB23);
        }
    }
#pragma unroll
    for (int u = 0; u < 9; u++) {
        ulonglong2 s = S[M3 + M2 + u];
        FMA2(rA01, s.x, x2A[u], rA01);
        FMA2(rA23, s.y, x2A[u], rA23);
        FMA2(rB01, s.x, x2B[u], rB01);
        FMA2(rB23, s.y, x2B[u], rB23);
    }

    const size_t st = (size_t)CC * NMAX;
    if (vA) {
        float f0, f1, f2, f3;
        UNPACK2(f0, f1, rA01); UNPACK2(f2, f3, rA23);
        size_t base = (size_t)c * NMAX + posA;
        d_Og[base] = f0; d_Og[st + base] = f1;
        d_Og[2 * st + base] = f2; d_Og[3 * st + base] = f3;
    }
    if (vB) {
        float f0, f1, f2, f3;
        UNPACK2(f0, f1, rB01); UNPACK2(f2, f3, rB23);
        size_t base = (size_t)c * NMAX + posB;
        d_Og[base] = f0; d_Og[st + base] = f1;
        d_Og[2 * st + base] = f2; d_Og[3 * st + base] = f3;
    }
}

// ---------------------------------------------------------------- linear + residual
#define BM 64
#define BN 64
#define BK 16
// shared layout (floats): As region [0, 3*BK*BM), Bs region [3*BK*BM, +BK*BN)
#define SH_AS_STRIDE (BK * BM)
#define SH_BS_OFF    (3 * BK * BM)

__device__ __forceinline__ void lin0_body(float* shbuf,
                                          const float* __restrict__ lin0,
                                          const float* __restrict__ sc,
                                          float* __restrict__ out, int n) {
    float (*As)[BM] = reinterpret_cast<float(*)[BM]>(shbuf);
    float (*Bs)[BN] = reinterpret_cast<float(*)[BN]>(shbuf + SH_BS_OFF);
    int tid = threadIdx.x;
    int tr = tid / 16, tc = tid % 16;
    int rowBase = blockIdx.y * BM;
    int colBase = blockIdx.x * BN;

    u64 acc[4][2] = {{0, 0}, {0, 0}, {0, 0}, {0, 0}};

    for (int k0 = 0; k0 < CC; k0 += BK) {
#pragma unroll
        for (int i = 0; i < 4; i++) {
            int idx = tid + i * 256;
            int kk = idx / BM, m = idx % BM;
            int r = rowBase + m;
            As[kk][m] = (r < n) ? d_Og[(size_t)(k0 + kk) * NMAX + r] : 0.f;
        }
#pragma unroll
        for (int i = 0; i < 4; i++) {
            int idx = tid + i * 256;
            int kk = idx / BN, j = idx % BN;
            Bs[kk][j] = lin0[(k0 + kk) * CC + colBase + j];
        }
        __syncthreads();
#pragma unroll
        for (int kk = 0; kk < BK; kk++) {
            float4 av = *reinterpret_cast<const float4*>(&As[kk][tr * 4]);
            u64 a2[4];
            SPLAT2(a2[0], av.x); SPLAT2(a2[1], av.y);
            SPLAT2(a2[2], av.z); SPLAT2(a2[3], av.w);
            ulonglong2 bv = *reinterpret_cast<const ulonglong2*>(&Bs[kk][tc * 4]);
#pragma unroll
            for (int i = 0; i < 4; i++) {
                FMA2(acc[i][0], a2[i], bv.x, acc[i][0]);
                FMA2(acc[i][1], a2[i], bv.y, acc[i][1]);
            }
        }
        __syncthreads();
    }

#pragma unroll
    for (int i = 0; i < 4; i++) {
        int r = rowBase + tr * 4 + i;
        if (r >= n) continue;
        int b = d_nodeC[r];
        size_t o = (size_t)b * 512 + colBase + tc * 4;
        float4 scv = *reinterpret_cast<const float4*>(&sc[o]);
        float f0, f1, f2, f3;
        UNPACK2(f0, f1, acc[i][0]); UNPACK2(f2, f3, acc[i][1]);
        float4 ov = make_float4(f0 * INV_SQRT_C + scv.x, f1 * INV_SQRT_C + scv.y,
                                f2 * INV_SQRT_C + scv.z, f3 * INV_SQRT_C + scv.w);
        *reinterpret_cast<float4*>(&out[o]) = ov;
    }
}

__device__ __forceinline__ void lin1_body(float* shbuf,
                                          const float* __restrict__ lin1,
                                          const float* __restrict__ sc,
                                          float* __restrict__ out, int n) {
    float (*Bs)[BN] = reinterpret_cast<float(*)[BN]>(shbuf + SH_BS_OFF);
    int tid = threadIdx.x;
    int tr = tid / 16, tc = tid % 16;
    int rowBase = blockIdx.y * BM;
    int colBase = blockIdx.x * BN;

    u64 acc[3][4][2];
#pragma unroll
    for (int d = 0; d < 3; d++)
#pragma unroll
        for (int i = 0; i < 4; i++) { acc[d][i][0] = 0; acc[d][i][1] = 0; }

    const size_t st = (size_t)CC * NMAX;
    for (int k0 = 0; k0 < CC; k0 += BK) {
#pragma unroll
        for (int d = 0; d < 3; d++) {
            const float* A = d_Og + (size_t)(d + 1) * st;
            float (*Asd)[BM] = reinterpret_cast<float(*)[BM]>(shbuf + d * SH_AS_STRIDE);
#pragma unroll
            for (int i = 0; i < 4; i++) {
                int idx = tid + i * 256;
                int kk = idx / BM, m = idx % BM;
                int r = rowBase + m;
                Asd[kk][m] = (r < n) ? A[(size_t)(k0 + kk) * NMAX + r] : 0.f;
            }
        }
#pragma unroll
        for (int i = 0; i < 4; i++) {
            int idx = tid + i * 256;
            int kk = idx / BN, j = idx % BN;
            Bs[kk][j] = lin1[(k0 + kk) * CC + colBase + j];
        }
        __syncthreads();
#pragma unroll
        for (int kk = 0; kk < BK; kk++) {
            ulonglong2 bv = *reinterpret_cast<const ulonglong2*>(&Bs[kk][tc * 4]);
#pragma unroll
            for (int d = 0; d < 3; d++) {
                const float* Asd = shbuf + d * SH_AS_STRIDE + kk * BM;
                float4 av = *reinterpret_cast<const float4*>(&Asd[tr * 4]);
                u64 a2[4];
                SPLAT2(a2[0], av.x); SPLAT2(a2[1], av.y);
                SPLAT2(a2[2], av.z); SPLAT2(a2[3], av.w);
#pragma unroll
                for (int i = 0; i < 4; i++) {
                    FMA2(acc[d][i][0], a2[i], bv.x, acc[d][i][0]);
                    FMA2(acc[d][i][1], a2[i], bv.y, acc[d][i][1]);
                }
            }
        }
        __syncthreads();
    }

#pragma unroll
    for (int i = 0; i < 4; i++) {
        int r = rowBase + tr * 4 + i;
        if (r >= n) continue;
        int b = d_nodeC[r];
        float f[12];
#pragma unroll
        for (int d = 0; d < 3; d++) {
            float l0, h0, l1, h1;
            UNPACK2(l0, h0, acc[d][i][0]);
            UNPACK2(l1, h1, acc[d][i][1]);
            f[0 * 3 + d] = l0; f[1 * 3 + d] = h0;
            f[2 * 3 + d] = l1; f[3 * 3 + d] = h1;
        }
        size_t base = (size_t)b * 512 + CC + (size_t)(colBase + tc * 4) * 3;
#pragma unroll
        for (int q = 0; q < 3; q++) {
            float4 scv = *reinterpret_cast<const float4*>(&sc[base + q * 4]);
            float4 ov = make_float4(f[q * 4 + 0] * INV_SQRT_C + scv.x,
                                    f[q * 4 + 1] * INV_SQRT_C + scv.y,
                                    f[q * 4 + 2] * INV_SQRT_C + scv.z,
                                    f[q * 4 + 3] * INV_SQRT_C + scv.w);
            *reinterpret_cast<float4*>(&out[base + q * 4]) = ov;
        }
    }
}

__global__ __launch_bounds__(256) void k_lin(const float* __restrict__ lin0,
                                             const float* __restrict__ lin1,
                                             const float* __restrict__ sc,
                                             float* __restrict__ out, int n) {
    __shared__ __align__(16) float shbuf[SH_BS_OFF + BK * BN];  // 16 KB
    if (blockIdx.z == 0) lin0_body(shbuf, lin0, sc, out, n);
    else                 lin1_body(shbuf, lin1, sc, out, n);
}

// ---------------------------------------------------------------- launch
extern "C" void kernel_launch(void* const* d_in, const int* in_sizes, int n_in,
                              void* d_out, int out_size) {
    const float* node_feats = (const float*)d_in[0];
    const float* node_attrs = (const float*)d_in[1];
    const float* sc         = (const float*)d_in[2];
    const float* U3_0 = (const float*)d_in[3];
    const float* U2_0 = (const float*)d_in[4];
    const float* U1_0 = (const float*)d_in[5];
    const float* w3_0 = (const float*)d_in[6];
    const float* w2_0 = (const float*)d_in[7];
    const float* w1_0 = (const float*)d_in[8];
    const float* U3_1 = (const float*)d_in[9];
    const float* U2_1 = (const float*)d_in[10];
    const float* U1_1 = (const float*)d_in[11];
    const float* w3_1 = (const float*)d_in[12];
    const float* w2_1 = (const float*)d_in[13];
    const float* w1_1 = (const float*)d_in[14];
    const float* lin_w0 = (const float*)d_in[15];
    const float* lin_w1 = (const float*)d_in[16];

    int n = in_sizes[0] / (CC * LL);

    k_init<<<1, 32>>>();
    k_assign<<<(n + 255) / 256, 256>>>(node_attrs, n);

    dim3 gc((MTOT + MCH - 1) / MCH, EE);
    k_coeffs<<<gc, 128>>>(U3_0, U2_0, U1_0, w3_0, w2_0, w1_0,
                          U3_1, U2_1, U1_1, w3_1, w2_1, w1_1);

    int maxT = (n + 63) / 64 + EE;
    k_main<<<dim3(CC / 4, maxT), 128>>>(node_feats);

    dim3 gl(CC / BN, (n + BM - 1) / BM, 2);
    k_lin<<<gl, 256>>>(lin_w0, lin_w1, sc, (float*)d_out, n);
}

// round 12
// speedup vs baseline: 2.0944x; 1.0524x over previous
#include <cuda_runtime.h>
#include <cstdint>

#define CC 128
#define LL 9
#define EE 5
#define NMAX 10000
#define M3 165
#define M2 45
#define M1 9
#define MTOT (M3 + M2 + M1)   // 219
#define INV_SQRT_C 0.08838834764831845f
#define NPT 4                 // nodes per thread in k_main
#define TILE (32 * NPT)       // 128-node element-homogeneous tiles

typedef unsigned long long u64;

// packed f32x2 helpers (SASS FFMA2 — only via PTX)
#define FMA2(d, a, b, c) asm("fma.rn.f32x2 %0, %1, %2, %3;" : "=l"(d) : "l"(a), "l"(b), "l"(c))
#define MUL2(d, a, b)    asm("mul.rn.f32x2 %0, %1, %2;" : "=l"(d) : "l"(a), "l"(b))
#define SPLAT2(d, s)     asm("mov.b64 %0, {%1, %1};" : "=l"(d) : "r"(__float_as_uint(s)))
#define UNPACK2(lo, hi, v) do { unsigned _lo, _hi; \
    asm("mov.b64 {%0, %1}, %2;" : "=r"(_lo), "=r"(_hi) : "l"(v)); \
    lo = __uint_as_float(_lo); hi = __uint_as_float(_hi); } while (0)

static __device__ int    d_cnt[EE];
static __device__ int    d_off[EE + 1];       // exact prefix of counts
static __device__ int    d_tileOff[EE + 1];   // prefix of TILE-node tiles
static __device__ int    d_nodeList[EE * NMAX];
static __device__ int    d_nodeC[NMAX];       // compact pos -> node id
static __device__ float4 d_S3[EE * CC * M3];
static __device__ float4 d_S2[EE * CC * M2];
static __device__ float4 d_S1[EE * CC * M1];
static __device__ float  d_Og[4 * (size_t)CC * NMAX];  // [slot][c][pos]

// ---------------------------------------------------------------- bucketing
__global__ void k_init() {
    if (threadIdx.x < EE) d_cnt[threadIdx.x] = 0;
}

__global__ void k_assign(const float* __restrict__ attrs, int n) {
    int b = blockIdx.x * blockDim.x + threadIdx.x;
    if (b >= n) return;
    int e = 0; float best = -1.0f;
#pragma unroll
    for (int j = 0; j < EE; j++) {
        float v = attrs[b * EE + j];
        if (v > best) { best = v; e = j; }
    }
    int pos = atomicAdd(&d_cnt[e], 1);
    d_nodeList[e * NMAX + pos] = b;
}

// ---------------------------------------------------------------- monomial decode
__device__ __forceinline__ void decode3(int m, int& U, int& V, int& W) {
    int cnt = 0;
    U = V = W = 0;
    for (int a = 0; a < LL; a++) {
        int blk = (LL - a) * (LL - a + 1) / 2;
        if (m < cnt + blk) {
            U = a;
            int r = m - cnt, c2 = 0;
            for (int b = a; b < LL; b++) {
                int run = LL - b;
                if (r < c2 + run) { V = b; W = b + (r - c2); return; }
                c2 += run;
            }
            return;
        }
        cnt += blk;
    }
}
__device__ __forceinline__ void decode2(int m, int& U, int& V) {
    int cnt = 0;
    U = V = 0;
    for (int a = 0; a < LL; a++) {
        int run = LL - a;
        if (m < cnt + run) { U = a; V = a + (m - cnt); return; }
        cnt += run;
    }
}

// ---------------------------------------------------------------- coefficient build
// Fuses: prefix-scan (block 0,0), symmetrized-U table build (per m-chunk, in shared),
// and the S = T·w contraction. Grid: (ceil(MTOT/MCH), EE), 128 threads.
#define MCH 16
__global__ __launch_bounds__(128) void k_coeffs(
        const float* __restrict__ U3_0, const float* __restrict__ U2_0, const float* __restrict__ U1_0,
        const float* __restrict__ w3_0, const float* __restrict__ w2_0, const float* __restrict__ w1_0,
        const float* __restrict__ U3_1, const float* __restrict__ U2_1, const float* __restrict__ U1_1,
        const float* __restrict__ w3_1, const float* __restrict__ w2_1, const float* __restrict__ w1_1) {

    // folded k_off: prefix scan (d_cnt is consumed read-only; k_init re-zeroes each run)
    if (blockIdx.x == 0 && blockIdx.y == 0 && threadIdx.x == 0) {
        int off = 0, toff = 0;
        d_off[0] = 0; d_tileOff[0] = 0;
#pragma unroll
        for (int e = 0; e < EE; e++) {
            int cnt = d_cnt[e];
            off += cnt; toff += (cnt + TILE - 1) / TILE;
            d_off[e + 1] = off; d_tileOff[e + 1] = toff;
        }
    }

    int e = blockIdx.y, c = threadIdx.x;
    int m0 = blockIdx.x * MCH;
    int m1 = m0 + MCH; if (m1 > MTOT) m1 = MTOT;

    // stage symmetrized tables for this m-chunk:
    // shA[mi][k] : cubic T30 (k<10) or quadratic T20 (k<3)
    // shB[d][mi][k] : cubic T31 (k<12) or quadratic T21 (k<4)
    __shared__ float shA[MCH][10];
    __shared__ float shB[3][MCH][12];

    for (int i = threadIdx.x; i < MCH * 10; i += 128) {
        int mi = i / 10, k = i % 10;
        int m = m0 + mi;
        float val = 0.f;
        if (m < M3) {
            int U, V, W; decode3(m, U, V, W);
            int pa[6] = {U, U, V, V, W, W}, pb[6] = {V, W, U, W, U, V}, pg[6] = {W, V, W, U, V, U};
            float s = 0.f;
#pragma unroll
            for (int p = 0; p < 6; p++) s += U3_0[((pa[p] * LL + pb[p]) * LL + pg[p]) * 10 + k];
            float dup = (U == V && V == W) ? (1.f / 6.f) : ((U == V || V == W || U == W) ? 0.5f : 1.f);
            val = s * dup;
        } else if (m < M3 + M2 && k < 3) {
            int U, V; decode2(m - M3, U, V);
            float s = U2_0[(U * LL + V) * 3 + k] + U2_0[(V * LL + U) * 3 + k];
            val = s * ((U == V) ? 0.5f : 1.f);
        }
        shA[mi][k] = val;
    }
    for (int i = threadIdx.x; i < 3 * MCH * 12; i += 128) {
        int d = i / (MCH * 12), r = i % (MCH * 12);
        int mi = r / 12, k = r % 12;
        int m = m0 + mi;
        float val = 0.f;
        if (m < M3) {
            int U, V, W; decode3(m, U, V, W);
            int pa[6] = {U, U, V, V, W, W}, pb[6] = {V, W, U, W, U, V}, pg[6] = {W, V, W, U, V, U};
            float s = 0.f;
#pragma unroll
            for (int p = 0; p < 6; p++) s += U3_1[(((d * LL + pa[p]) * LL + pb[p]) * LL + pg[p]) * 12 + k];
            float dup = (U == V && V == W) ? (1.f / 6.f) : ((U == V || V == W || U == W) ? 0.5f : 1.f);
            val = s * dup;
        } else if (m < M3 + M2 && k < 4) {
            int U, V; decode2(m - M3, U, V);
            float s = U2_1[((d * LL + U) * LL + V) * 4 + k] + U2_1[((d * LL + V) * LL + U) * 4 + k];
            val = s * ((U == V) ? 0.5f : 1.f);
        }
        shB[d][mi][k] = val;
    }
    __syncthreads();

    // per-channel weights
    float wa0[10], wa1[12], wb0[3], wb1[4];
#pragma unroll
    for (int k = 0; k < 10; k++) wa0[k] = w3_0[(e * 10 + k) * CC + c];
#pragma unroll
    for (int k = 0; k < 12; k++) wa1[k] = w3_1[(e * 12 + k) * CC + c];
#pragma unroll
    for (int k = 0; k < 3; k++)  wb0[k] = w2_0[(e * 3 + k) * CC + c];
#pragma unroll
    for (int k = 0; k < 4; k++)  wb1[k] = w2_1[(e * 4 + k) * CC + c];
    float wc0 = w1_0[e * CC + c], wc1 = w1_1[e * CC + c];

    for (int m = m0; m < m1; m++) {
        int mi = m - m0;
        if (m < M3) {
            float s0 = 0.f;
#pragma unroll
            for (int k = 0; k < 10; k++) s0 += shA[mi][k] * wa0[k];
            float sd[3];
#pragma unroll
            for (int d = 0; d < 3; d++) {
                float a = 0.f;
#pragma unroll
                for (int k = 0; k < 12; k++) a += shB[d][mi][k] * wa1[k];
                sd[d] = a;
            }
            d_S3[(e * CC + c) * M3 + m] = make_float4(s0, sd[0], sd[1], sd[2]);
        } else if (m < M3 + M2) {
            int mm = m - M3;
            float s0 = 0.f;
#pragma unroll
            for (int k = 0; k < 3; k++) s0 += shA[mi][k] * wb0[k];
            float sd[3];
#pragma unroll
            for (int d = 0; d < 3; d++) {
                float a = 0.f;
#pragma unroll
                for (int k = 0; k < 4; k++) a += shB[d][mi][k] * wb1[k];
                sd[d] = a;
            }
            d_S2[(e * CC + c) * M2 + mm] = make_float4(s0, sd[0], sd[1], sd[2]);
        } else {
            int u = m - M3 - M2;
            d_S1[(e * CC + c) * M1 + u] = make_float4(
                U1_0[u] * wc0, U1_1[0 * LL + u] * wc1,
                U1_1[1 * LL + u] * wc1, U1_1[2 * LL + u] * wc1);
        }
    }
}

// ---------------------------------------------------------------- main contraction
// 4 warps/block; warp -> channel, lane -> NPT nodes (lane + j*32) within a
// TILE-node element-homogeneous tile. 4 d-slots packed as 2x f32x2; each
// coefficient LDS.128 feeds 2*NPT FFMA2s (LDS amortization).
__global__ __launch_bounds__(128) void k_main(const float* __restrict__ xfeat) {
    int t = blockIdx.y;
    if (t >= d_tileOff[EE]) return;
    int e = 0;
    while (t >= d_tileOff[e + 1]) e++;

    int warp = threadIdx.x >> 5, lane = threadIdx.x & 31;
    int c = blockIdx.x * 4 + warp;

    __shared__ __align__(16) float4 sh[4][MTOT];
    {
        const float4* s3 = &d_S3[(e * CC + c) * M3];
        for (int i = lane; i < M3; i += 32) sh[warp][i] = s3[i];
        const float4* s2 = &d_S2[(e * CC + c) * M2];
        for (int i = lane; i < M2; i += 32) sh[warp][M3 + i] = s2[i];
        if (lane < M1) sh[warp][M3 + M2 + lane] = d_S1[(e * CC + c) * M1 + lane];
    }
    __syncwarp();

    int cnt = d_off[e + 1] - d_off[e];
    int lt = t - d_tileOff[e];

    bool v[NPT];
    int pos[NPT];
    u64 x2[NPT][9];
#pragma unroll
    for (int j = 0; j < NPT; j++) {
        int ni = lt * TILE + lane + j * 32;
        v[j] = ni < cnt;
        int b = d_nodeList[e * NMAX + (v[j] ? ni : 0)];
        pos[j] = d_off[e] + ni;
        if (blockIdx.x == 0 && warp == 0 && v[j]) d_nodeC[pos[j]] = b;
        const float* p = xfeat + ((size_t)b * CC + c) * LL;
#pragma unroll
        for (int w = 0; w < 9; w++) SPLAT2(x2[j][w], p[w]);
    }

    const ulonglong2* S = reinterpret_cast<const ulonglong2*>(sh[warp]);
    u64 r0[NPT], r1[NPT];
#pragma unroll
    for (int j = 0; j < NPT; j++) { r0[j] = 0; r1[j] = 0; }

    int m3 = 0, m2 = M3;
#pragma unroll
    for (int u = 0; u < 9; u++) {
#pragma unroll
        for (int vv = u; vv < 9; vv++) {
            u64 p2[NPT];
#pragma unroll
            for (int j = 0; j < NPT; j++) MUL2(p2[j], x2[j][u], x2[j][vv]);
            ulonglong2 q = S[m2++];
            u64 i0[NPT], i1[NPT];
#pragma unroll
            for (int j = 0; j < NPT; j++) { i0[j] = q.x; i1[j] = q.y; }
#pragma unroll
            for (int w = vv; w < 9; w++) {
                ulonglong2 s = S[m3++];
#pragma unroll
                for (int j = 0; j < NPT; j++) {
                    FMA2(i0[j], s.x, x2[j][w], i0[j]);
                    FMA2(i1[j], s.y, x2[j][w], i1[j]);
                }
            }
#pragma unroll
            for (int j = 0; j < NPT; j++) {
                FMA2(r0[j], p2[j], i0[j], r0[j]);
                FMA2(r1[j], p2[j], i1[j], r1[j]);
            }
        }
    }
#pragma unroll
    for (int u = 0; u < 9; u++) {
        ulonglong2 s = S[M3 + M2 + u];
#pragma unroll
        for (int j = 0; j < NPT; j++) {
            FMA2(r0[j], s.x, x2[j][u], r0[j]);
            FMA2(r1[j], s.y, x2[j][u], r1[j]);
        }
    }

    const size_t st = (size_t)CC * NMAX;
#pragma unroll
    for (int j = 0; j < NPT; j++) {
        if (!v[j]) continue;
        float f0, f1, f2, f3;
        UNPACK2(f0, f1, r0[j]); UNPACK2(f2, f3, r1[j]);
        size_t base = (size_t)c * NMAX + pos[j];
        d_Og[base]          = f0;
        d_Og[st + base]     = f1;
        d_Og[2 * st + base] = f2;
        d_Og[3 * st + base] = f3;
    }
}

// ---------------------------------------------------------------- linear + residual
#define BM 64
#define BN 64
#define BK 16
// shared layout (floats): As region [0, 3*BK*BM), Bs region [3*BK*BM, +BK*BN)
#define SH_AS_STRIDE (BK * BM)
#define SH_BS_OFF    (3 * BK * BM)

__device__ __forceinline__ void lin0_body(float* shbuf,
                                          const float* __restrict__ lin0,
                                          const float* __restrict__ sc,
                                          float* __restrict__ out, int n) {
    float (*As)[BM] = reinterpret_cast<float(*)[BM]>(shbuf);
    float (*Bs)[BN] = reinterpret_cast<float(*)[BN]>(shbuf + SH_BS_OFF);
    int tid = threadIdx.x;
    int tr = tid / 16, tc = tid % 16;
    int rowBase = blockIdx.y * BM;
    int colBase = blockIdx.x * BN;

    u64 acc[4][2] = {{0, 0}, {0, 0}, {0, 0}, {0, 0}};

    for (int k0 = 0; k0 < CC; k0 += BK) {
#pragma unroll
        for (int i = 0; i < 4; i++) {
            int idx = tid + i * 256;
            int kk = idx / BM, m = idx % BM;
            int r = rowBase + m;
            As[kk][m] = (r < n) ? d_Og[(size_t)(k0 + kk) * NMAX + r] : 0.f;
        }
#pragma unroll
        for (int i = 0; i < 4; i++) {
            int idx = tid + i * 256;
            int kk = idx / BN, j = idx % BN;
            Bs[kk][j] = lin0[(k0 + kk) * CC + colBase + j];
        }
        __syncthreads();
#pragma unroll
        for (int kk = 0; kk < BK; kk++) {
            float4 av = *reinterpret_cast<const float4*>(&As[kk][tr * 4]);
            u64 a2[4];
            SPLAT2(a2[0], av.x); SPLAT2(a2[1], av.y);
            SPLAT2(a2[2], av.z); SPLAT2(a2[3], av.w);
            ulonglong2 bv = *reinterpret_cast<const ulonglong2*>(&Bs[kk][tc * 4]);
#pragma unroll
            for (int i = 0; i < 4; i++) {
                FMA2(acc[i][0], a2[i], bv.x, acc[i][0]);
                FMA2(acc[i][1], a2[i], bv.y, acc[i][1]);
            }
        }
        __syncthreads();
    }

#pragma unroll
    for (int i = 0; i < 4; i++) {
        int r = rowBase + tr * 4 + i;
        if (r >= n) continue;
        int b = d_nodeC[r];
        size_t o = (size_t)b * 512 + colBase + tc * 4;
        float4 scv = *reinterpret_cast<const float4*>(&sc[o]);
        float f0, f1, f2, f3;
        UNPACK2(f0, f1, acc[i][0]); UNPACK2(f2, f3, acc[i][1]);
        float4 ov = make_float4(f0 * INV_SQRT_C + scv.x, f1 * INV_SQRT_C + scv.y,
                                f2 * INV_SQRT_C + scv.z, f3 * INV_SQRT_C + scv.w);
        *reinterpret_cast<float4*>(&out[o]) = ov;
    }
}

__device__ __forceinline__ void lin1_body(float* shbuf,
                                          const float* __restrict__ lin1,
                                          const float* __restrict__ sc,
                                          float* __restrict__ out, int n) {
    float (*Bs)[BN] = reinterpret_cast<float(*)[BN]>(shbuf + SH_BS_OFF);
    int tid = threadIdx.x;
    int tr = tid / 16, tc = tid % 16;
    int rowBase = blockIdx.y * BM;
    int colBase = blockIdx.x * BN;

    u64 acc[3][4][2];
#pragma unroll
    for (int d = 0; d < 3; d++)
#pragma unroll
        for (int i = 0; i < 4; i++) { acc[d][i][0] = 0; acc[d][i][1] = 0; }

    const size_t st = (size_t)CC * NMAX;
    for (int k0 = 0; k0 < CC; k0 += BK) {
#pragma unroll
        for (int d = 0; d < 3; d++) {
            const float* A = d_Og + (size_t)(d + 1) * st;
            float (*Asd)[BM] = reinterpret_cast<float(*)[BM]>(shbuf + d * SH_AS_STRIDE);
#pragma unroll
            for (int i = 0; i < 4; i++) {
                int idx = tid + i * 256;
                int kk = idx / BM, m = idx % BM;
                int r = rowBase + m;
                Asd[kk][m] = (r < n) ? A[(size_t)(k0 + kk) * NMAX + r] : 0.f;
            }
        }
#pragma unroll
        for (int i = 0; i < 4; i++) {
            int idx = tid + i * 256;
            int kk = idx / BN, j = idx % BN;
            Bs[kk][j] = lin1[(k0 + kk) * CC + colBase + j];
        }
        __syncthreads();
#pragma unroll
        for (int kk = 0; kk < BK; kk++) {
            ulonglong2 bv = *reinterpret_cast<const ulonglong2*>(&Bs[kk][tc * 4]);
#pragma unroll
            for (int d = 0; d < 3; d++) {
                const float* Asd = shbuf + d * SH_AS_STRIDE + kk * BM;
                float4 av = *reinterpret_cast<const float4*>(&Asd[tr * 4]);
                u64 a2[4];
                SPLAT2(a2[0], av.x); SPLAT2(a2[1], av.y);
                SPLAT2(a2[2], av.z); SPLAT2(a2[3], av.w);
#pragma unroll
                for (int i = 0; i < 4; i++) {
                    FMA2(acc[d][i][0], a2[i], bv.x, acc[d][i][0]);
                    FMA2(acc[d][i][1], a2[i], bv.y, acc[d][i][1]);
                }
            }
        }
        __syncthreads();
    }

#pragma unroll
    for (int i = 0; i < 4; i++) {
        int r = rowBase + tr * 4 + i;
        if (r >= n) continue;
        int b = d_nodeC[r];
        float f[12];
#pragma unroll
        for (int d = 0; d < 3; d++) {
            float l0, h0, l1, h1;
            UNPACK2(l0, h0, acc[d][i][0]);
            UNPACK2(l1, h1, acc[d][i][1]);
            f[0 * 3 + d] = l0; f[1 * 3 + d] = h0;
            f[2 * 3 + d] = l1; f[3 * 3 + d] = h1;
        }
        size_t base = (size_t)b * 512 + CC + (size_t)(colBase + tc * 4) * 3;
#pragma unroll
        for (int q = 0; q < 3; q++) {
            float4 scv = *reinterpret_cast<const float4*>(&sc[base + q * 4]);
            float4 ov = make_float4(f[q * 4 + 0] * INV_SQRT_C + scv.x,
                                    f[q * 4 + 1] * INV_SQRT_C + scv.y,
                                    f[q * 4 + 2] * INV_SQRT_C + scv.z,
                                    f[q * 4 + 3] * INV_SQRT_C + scv.w);
            *reinterpret_cast<float4*>(&out[base + q * 4]) = ov;
        }
    }
}

__global__ __launch_bounds__(256) void k_lin(const float* __restrict__ lin0,
                                             const float* __restrict__ lin1,
                                             const float* __restrict__ sc,
                                             float* __restrict__ out, int n) {
    __shared__ __align__(16) float shbuf[SH_BS_OFF + BK * BN];  // 16 KB
    if (blockIdx.z == 0) lin0_body(shbuf, lin0, sc, out, n);
    else                 lin1_body(shbuf, lin1, sc, out, n);
}

// ---------------------------------------------------------------- launch
extern "C" void kernel_launch(void* const* d_in, const int* in_sizes, int n_in,
                              void* d_out, int out_size) {
    const float* node_feats = (const float*)d_in[0];
    const float* node_attrs = (const float*)d_in[1];
    const float* sc         = (const float*)d_in[2];
    const float* U3_0 = (const float*)d_in[3];
    const float* U2_0 = (const float*)d_in[4];
    const float* U1_0 = (const float*)d_in[5];
    const float* w3_0 = (const float*)d_in[6];
    const float* w2_0 = (const float*)d_in[7];
    const float* w1_0 = (const float*)d_in[8];
    const float* U3_1 = (const float*)d_in[9];
    const float* U2_1 = (const float*)d_in[10];
    const float* U1_1 = (const float*)d_in[11];
    const float* w3_1 = (const float*)d_in[12];
    const float* w2_1 = (const float*)d_in[13];
    const float* w1_1 = (const float*)d_in[14];
    const float* lin_w0 = (const float*)d_in[15];
    const float* lin_w1 = (const float*)d_in[16];

    int n = in_sizes[0] / (CC * LL);

    k_init<<<1, 32>>>();
    k_assign<<<(n + 255) / 256, 256>>>(node_attrs, n);

    dim3 gc((MTOT + MCH - 1) / MCH, EE);
    k_coeffs<<<gc, 128>>>(U3_0, U2_0, U1_0, w3_0, w2_0, w1_0,
                          U3_1, U2_1, U1_1, w3_1, w2_1, w1_1);

    int maxT = (n + TILE - 1) / TILE + EE;
    k_main<<<dim3(CC / 4, maxT), 128>>>(node_feats);

    dim3 gl(CC / BN, (n + BM - 1) / BM, 2);
    k_lin<<<gl, 256>>>(lin_w0, lin_w1, sc, (float*)d_out, n);
}

// round 17
// speedup vs baseline: 2.2453x; 1.0721x over previous
#include <cuda_runtime.h>
#include <cstdint>

#define CC 128
#define LL 9
#define EE 5
#define NMAX 10000
#define M3 165
#define M2 45
#define M1 9
#define MTOT (M3 + M2 + M1)   // 219
#define INV_SQRT_C 0.08838834764831845f
#define NPT 2                 // nodes per thread in k_main
#define TILE (32 * NPT)       // 64-node element-homogeneous tiles

typedef unsigned long long u64;

// packed f32x2 helpers (SASS FFMA2 — only via PTX)
#define FMA2(d, a, b, c) asm("fma.rn.f32x2 %0, %1, %2, %3;" : "=l"(d) : "l"(a), "l"(b), "l"(c))
#define MUL2(d, a, b)    asm("mul.rn.f32x2 %0, %1, %2;" : "=l"(d) : "l"(a), "l"(b))
#define SPLAT2(d, s)     asm("mov.b64 %0, {%1, %1};" : "=l"(d) : "r"(__float_as_uint(s)))
#define UNPACK2(lo, hi, v) do { unsigned _lo, _hi; \
    asm("mov.b64 {%0, %1}, %2;" : "=r"(_lo), "=r"(_hi) : "l"(v)); \
    lo = __uint_as_float(_lo); hi = __uint_as_float(_hi); } while (0)

static __device__ int    d_cnt[EE];
static __device__ int    d_off[EE + 1];       // exact prefix of counts
static __device__ int    d_tileOff[EE + 1];   // prefix of TILE-node tiles
static __device__ int    d_nodeList[EE * NMAX];
static __device__ int    d_nodeC[NMAX];       // compact pos -> node id
static __device__ float4 d_S3[EE * CC * M3];
static __device__ float4 d_S2[EE * CC * M2];
static __device__ float4 d_S1[EE * CC * M1];
static __device__ float  d_Og[4 * (size_t)CC * NMAX];  // [slot][c][pos]

// ---------------------------------------------------------------- bucketing
__global__ void k_init() {
    if (threadIdx.x < EE) d_cnt[threadIdx.x] = 0;
}

__global__ void k_assign(const float* __restrict__ attrs, int n) {
    int b = blockIdx.x * blockDim.x + threadIdx.x;
    if (b >= n) return;
    int e = 0; float best = -1.0f;
#pragma unroll
    for (int j = 0; j < EE; j++) {
        float v = attrs[b * EE + j];
        if (v > best) { best = v; e = j; }
    }
    int pos = atomicAdd(&d_cnt[e], 1);
    d_nodeList[e * NMAX + pos] = b;
}

// ---------------------------------------------------------------- monomial decode
__device__ __forceinline__ void decode3(int m, int& U, int& V, int& W) {
    int cnt = 0;
    U = V = W = 0;
    for (int a = 0; a < LL; a++) {
        int blk = (LL - a) * (LL - a + 1) / 2;
        if (m < cnt + blk) {
            U = a;
            int r = m - cnt, c2 = 0;
            for (int b = a; b < LL; b++) {
                int run = LL - b;
                if (r < c2 + run) { V = b; W = b + (r - c2); return; }
                c2 += run;
            }
            return;
        }
        cnt += blk;
    }
}
__device__ __forceinline__ void decode2(int m, int& U, int& V) {
    int cnt = 0;
    U = V = 0;
    for (int a = 0; a < LL; a++) {
        int run = LL - a;
        if (m < cnt + run) { U = a; V = a + (m - cnt); return; }
        cnt += run;
    }
}

// ---------------------------------------------------------------- coefficient build
// Fuses: prefix-scan (block 0,0), symmetrized-U table build (per m-chunk, in shared),
// and the S = T·w contraction. Grid: (ceil(MTOT/MCH), EE), 128 threads.
#define MCH 16
__global__ __launch_bounds__(128) void k_coeffs(
        const float* __restrict__ U3_0, const float* __restrict__ U2_0, const float* __restrict__ U1_0,
        const float* __restrict__ w3_0, const float* __restrict__ w2_0, const float* __restrict__ w1_0,
        const float* __restrict__ U3_1, const float* __restrict__ U2_1, const float* __restrict__ U1_1,
        const float* __restrict__ w3_1, const float* __restrict__ w2_1, const float* __restrict__ w1_1) {

    // folded k_off: prefix scan (d_cnt is consumed read-only; k_init re-zeroes each run)
    if (blockIdx.x == 0 && blockIdx.y == 0 && threadIdx.x == 0) {
        int off = 0, toff = 0;
        d_off[0] = 0; d_tileOff[0] = 0;
#pragma unroll
        for (int e = 0; e < EE; e++) {
            int cnt = d_cnt[e];
            off += cnt; toff += (cnt + TILE - 1) / TILE;
            d_off[e + 1] = off; d_tileOff[e + 1] = toff;
        }
    }

    int e = blockIdx.y, c = threadIdx.x;
    int m0 = blockIdx.x * MCH;
    int m1 = m0 + MCH; if (m1 > MTOT) m1 = MTOT;

    // stage symmetrized tables for this m-chunk:
    // shA[mi][k] : cubic T30 (k<10) or quadratic T20 (k<3)
    // shB[d][mi][k] : cubic T31 (k<12) or quadratic T21 (k<4)
    __shared__ float shA[MCH][10];
    __shared__ float shB[3][MCH][12];

    for (int i = threadIdx.x; i < MCH * 10; i += 128) {
        int mi = i / 10, k = i % 10;
        int m = m0 + mi;
        float val = 0.f;
        if (m < M3) {
            int U, V, W; decode3(m, U, V, W);
            int pa[6] = {U, U, V, V, W, W}, pb[6] = {V, W, U, W, U, V}, pg[6] = {W, V, W, U, V, U};
            float s = 0.f;
#pragma unroll
            for (int p = 0; p < 6; p++) s += U3_0[((pa[p] * LL + pb[p]) * LL + pg[p]) * 10 + k];
            float dup = (U == V && V == W) ? (1.f / 6.f) : ((U == V || V == W || U == W) ? 0.5f : 1.f);
            val = s * dup;
        } else if (m < M3 + M2 && k < 3) {
            int U, V; decode2(m - M3, U, V);
            float s = U2_0[(U * LL + V) * 3 + k] + U2_0[(V * LL + U) * 3 + k];
            val = s * ((U == V) ? 0.5f : 1.f);
        }
        shA[mi][k] = val;
    }
    for (int i = threadIdx.x; i < 3 * MCH * 12; i += 128) {
        int d = i / (MCH * 12), r = i % (MCH * 12);
        int mi = r / 12, k = r % 12;
        int m = m0 + mi;
        float val = 0.f;
        if (m < M3) {
            int U, V, W; decode3(m, U, V, W);
            int pa[6] = {U, U, V, V, W, W}, pb[6] = {V, W, U, W, U, V}, pg[6] = {W, V, W, U, V, U};
            float s = 0.f;
#pragma unroll
            for (int p = 0; p < 6; p++) s += U3_1[(((d * LL + pa[p]) * LL + pb[p]) * LL + pg[p]) * 12 + k];
            float dup = (U == V && V == W) ? (1.f / 6.f) : ((U == V || V == W || U == W) ? 0.5f : 1.f);
            val = s * dup;
        } else if (m < M3 + M2 && k < 4) {
            int U, V; decode2(m - M3, U, V);
            float s = U2_1[((d * LL + U) * LL + V) * 4 + k] + U2_1[((d * LL + V) * LL + U) * 4 + k];
            val = s * ((U == V) ? 0.5f : 1.f);
        }
        shB[d][mi][k] = val;
    }
    __syncthreads();

    // per-channel weights
    float wa0[10], wa1[12], wb0[3], wb1[4];
#pragma unroll
    for (int k = 0; k < 10; k++) wa0[k] = w3_0[(e * 10 + k) * CC + c];
#pragma unroll
    for (int k = 0; k < 12; k++) wa1[k] = w3_1[(e * 12 + k) * CC + c];
#pragma unroll
    for (int k = 0; k < 3; k++)  wb0[k] = w2_0[(e * 3 + k) * CC + c];
#pragma unroll
    for (int k = 0; k < 4; k++)  wb1[k] = w2_1[(e * 4 + k) * CC + c];
    float wc0 = w1_0[e * CC + c], wc1 = w1_1[e * CC + c];

    for (int m = m0; m < m1; m++) {
        int mi = m - m0;
        if (m < M3) {
            float s0 = 0.f;
#pragma unroll
            for (int k = 0; k < 10; k++) s0 += shA[mi][k] * wa0[k];
            float sd[3];
#pragma unroll
            for (int d = 0; d < 3; d++) {
                float a = 0.f;
#pragma unroll
                for (int k = 0; k < 12; k++) a += shB[d][mi][k] * wa1[k];
                sd[d] = a;
            }
            d_S3[(e * CC + c) * M3 + m] = make_float4(s0, sd[0], sd[1], sd[2]);
        } else if (m < M3 + M2) {
            int mm = m - M3;
            float s0 = 0.f;
#pragma unroll
            for (int k = 0; k < 3; k++) s0 += shA[mi][k] * wb0[k];
            float sd[3];
#pragma unroll
            for (int d = 0; d < 3; d++) {
                float a = 0.f;
#pragma unroll
                for (int k = 0; k < 4; k++) a += shB[d][mi][k] * wb1[k];
                sd[d] = a;
            }
            d_S2[(e * CC + c) * M2 + mm] = make_float4(s0, sd[0], sd[1], sd[2]);
        } else {
            int u = m - M3 - M2;
            d_S1[(e * CC + c) * M1 + u] = make_float4(
                U1_0[u] * wc0, U1_1[0 * LL + u] * wc1,
                U1_1[1 * LL + u] * wc1, U1_1[2 * LL + u] * wc1);
        }
    }
}

// ---------------------------------------------------------------- main contraction
// 4 warps/block; warp -> channel (c0 = 4*blockIdx.x + warp), lane -> NPT nodes
// within a TILE-node element-homogeneous tile. x staged cooperatively through
// shared: the block's 4 channels are 36 CONTIGUOUS floats per node (16B-aligned),
// loaded as float4 and scattered into transposed shX[c][l][node] for
// conflict-free per-thread reads. Kills the 32-line/warp LDG gather.
// All loops strictly bounded (no data-dependent unbounded search).
__global__ __launch_bounds__(128) void k_main(const float* __restrict__ xfeat) {
    int t = blockIdx.y;
    if (t >= d_tileOff[EE]) return;

    // bounded element search: e = largest bucket with d_tileOff[e] <= t
    int e = 0;
#pragma unroll
    for (int q = 1; q < EE; q++)
        if (t >= d_tileOff[q]) e = q;

    int tid = threadIdx.x;
    int warp = tid >> 5, lane = tid & 31;
    int c = blockIdx.x * 4 + warp;

    __shared__ __align__(16) float4 sh[4][MTOT];
    __shared__ int   shNode[TILE];
    __shared__ float shX[4][LL][TILE];

    int cnt = d_off[e + 1] - d_off[e];
    if (cnt < 0) cnt = 0;
    int lt = t - d_tileOff[e];

    // stage node ids (+ emit compact pos->node map once)
    if (tid < TILE) {
        int ni = lt * TILE + tid;
        bool ok = (ni >= 0) && (ni < cnt);
        int b = d_nodeList[e * NMAX + (ok ? ni : 0)];
        shNode[tid] = b;
        if (blockIdx.x == 0 && ok) d_nodeC[d_off[e] + ni] = b;
    }
    // coefficient staging (per warp, its own channel)
    {
        const float4* s3 = &d_S3[(e * CC + c) * M3];
        for (int i = lane; i < M3; i += 32) sh[warp][i] = s3[i];
        const float4* s2 = &d_S2[(e * CC + c) * M2];
        for (int i = lane; i < M2; i += 32) sh[warp][M3 + i] = s2[i];
        if (lane < M1) sh[warp][M3 + M2 + lane] = d_S1[(e * CC + c) * M1 + lane];
    }
    __syncthreads();

    // stage x: per node, 36 contiguous floats (channels c0..c0+3 × 9 l) = 9 float4
    {
        int c0 = blockIdx.x * 4;
        for (int i = tid; i < TILE * 9; i += 128) {
            int node = i / 9, q = i % 9;
            int b = shNode[node];
            float4 vq = *reinterpret_cast<const float4*>(
                xfeat + ((size_t)b * CC + c0) * LL + q * 4);
            float vals[4] = {vq.x, vq.y, vq.z, vq.w};
#pragma unroll
            for (int r = 0; r < 4; r++) {
                int f = q * 4 + r;
                shX[f / 9][f % 9][node] = vals[r];
            }
        }
    }
    __syncthreads();

    bool v[NPT];
    int pos[NPT];
    u64 x2[NPT][9];
#pragma unroll
    for (int j = 0; j < NPT; j++) {
        int nloc = lane + j * 32;
        int ni = lt * TILE + nloc;
        v[j] = ni < cnt;
        pos[j] = d_off[e] + ni;
#pragma unroll
        for (int w = 0; w < 9; w++) SPLAT2(x2[j][w], shX[warp][w][nloc]);
    }

    const ulonglong2* S = reinterpret_cast<const ulonglong2*>(sh[warp]);
    u64 r0[NPT], r1[NPT];
#pragma unroll
    for (int j = 0; j < NPT; j++) { r0[j] = 0; r1[j] = 0; }

    int m3 = 0, m2 = M3;
#pragma unroll
    for (int u = 0; u < 9; u++) {
#pragma unroll
        for (int vv = u; vv < 9; vv++) {
            u64 p2[NPT];
#pragma unroll
            for (int j = 0; j < NPT; j++) MUL2(p2[j], x2[j][u], x2[j][vv]);
            ulonglong2 q = S[m2++];
            u64 i0[NPT], i1[NPT];
#pragma unroll
            for (int j = 0; j < NPT; j++) { i0[j] = q.x; i1[j] = q.y; }
#pragma unroll
            for (int w = vv; w < 9; w++) {
                ulonglong2 s = S[m3++];
#pragma unroll
                for (int j = 0; j < NPT; j++) {
                    FMA2(i0[j], s.x, x2[j][w], i0[j]);
                    FMA2(i1[j], s.y, x2[j][w], i1[j]);
                }
            }
#pragma unroll
            for (int j = 0; j < NPT; j++) {
                FMA2(r0[j], p2[j], i0[j], r0[j]);
                FMA2(r1[j], p2[j], i1[j], r1[j]);
            }
        }
    }
#pragma unroll
    for (int u = 0; u < 9; u++) {
        ulonglong2 s = S[M3 + M2 + u];
#pragma unroll
        for (int j = 0; j < NPT; j++) {
            FMA2(r0[j], s.x, x2[j][u], r0[j]);
            FMA2(r1[j], s.y, x2[j][u], r1[j]);
        }
    }

    const size_t st = (size_t)CC * NMAX;
#pragma unroll
    for (int j = 0; j < NPT; j++) {
        if (!v[j]) continue;
        float f0, f1, f2, f3;
        UNPACK2(f0, f1, r0[j]); UNPACK2(f2, f3, r1[j]);
        size_t base = (size_t)c * NMAX + pos[j];
        d_Og[base]          = f0;
        d_Og[st + base]     = f1;
        d_Og[2 * st + base] = f2;
        d_Og[3 * st + base] = f3;
    }
}

// ---------------------------------------------------------------- linear + residual
#define BM 64
#define BN 64
#define BK 16
// shared layout (floats): As region [0, 3*BK*BM), Bs region [3*BK*BM, +BK*BN)
#define SH_AS_STRIDE (BK * BM)
#define SH_BS_OFF    (3 * BK * BM)

__device__ __forceinline__ void lin0_body(float* shbuf,
                                          const float* __restrict__ lin0,
                                          const float* __restrict__ sc,
                                          float* __restrict__ out, int n) {
    float (*As)[BM] = reinterpret_cast<float(*)[BM]>(shbuf);
    float (*Bs)[BN] = reinterpret_cast<float(*)[BN]>(shbuf + SH_BS_OFF);
    int tid = threadIdx.x;
    int tr = tid / 16, tc = tid % 16;
    int rowBase = blockIdx.y * BM;
    int colBase = blockIdx.x * BN;

    u64 acc[4][2] = {{0, 0}, {0, 0}, {0, 0}, {0, 0}};

    for (int k0 = 0; k0 < CC; k0 += BK) {
#pragma unroll
        for (int i = 0; i < 4; i++) {
            int idx = tid + i * 256;
            int kk = idx / BM, m = idx % BM;
            int r = rowBase + m;
            As[kk][m] = (r < n) ? d_Og[(size_t)(k0 + kk) * NMAX + r] : 0.f;
        }
#pragma unroll
        for (int i = 0; i < 4; i++) {
            int idx = tid + i * 256;
            int kk = idx / BN, j = idx % BN;
            Bs[kk][j] = lin0[(k0 + kk) * CC + colBase + j];
        }
        __syncthreads();
#pragma unroll
        for (int kk = 0; kk < BK; kk++) {
            float4 av = *reinterpret_cast<const float4*>(&As[kk][tr * 4]);
            u64 a2[4];
            SPLAT2(a2[0], av.x); SPLAT2(a2[1], av.y);
            SPLAT2(a2[2], av.z); SPLAT2(a2[3], av.w);
            ulonglong2 bv = *reinterpret_cast<const ulonglong2*>(&Bs[kk][tc * 4]);
#pragma unroll
            for (int i = 0; i < 4; i++) {
                FMA2(acc[i][0], a2[i], bv.x, acc[i][0]);
                FMA2(acc[i][1], a2[i], bv.y, acc[i][1]);
            }
        }
        __syncthreads();
    }

#pragma unroll
    for (int i = 0; i < 4; i++) {
        int r = rowBase + tr * 4 + i;
        if (r >= n) continue;
        int b = d_nodeC[r];
        size_t o = (size_t)b * 512 + colBase + tc * 4;
        float4 scv = *reinterpret_cast<const float4*>(&sc[o]);
        float f0, f1, f2, f3;
        UNPACK2(f0, f1, acc[i][0]); UNPACK2(f2, f3, acc[i][1]);
        float4 ov = make_float4(f0 * INV_SQRT_C + scv.x, f1 * INV_SQRT_C + scv.y,
                                f2 * INV_SQRT_C + scv.z, f3 * INV_SQRT_C + scv.w);
        *reinterpret_cast<float4*>(&out[o]) = ov;
    }
}

__device__ __forceinline__ void lin1_body(float* shbuf,
                                          const float* __restrict__ lin1,
                                          const float* __restrict__ sc,
                                          float* __restrict__ out, int n) {
    float (*Bs)[BN] = reinterpret_cast<float(*)[BN]>(shbuf + SH_BS_OFF);
    int tid = threadIdx.x;
    int tr = tid / 16, tc = tid % 16;
    int rowBase = blockIdx.y * BM;
    int colBase = blockIdx.x * BN;

    u64 acc[3][4][2];
#pragma unroll
    for (int d = 0; d < 3; d++)
#pragma unroll
        for (int i = 0; i < 4; i++) { acc[d][i][0] = 0; acc[d][i][1] = 0; }

    const size_t st = (size_t)CC * NMAX;
    for (int k0 = 0; k0 < CC; k0 += BK) {
#pragma unroll
        for (int d = 0; d < 3; d++) {
            const float* A = d_Og + (size_t)(d + 1) * st;
            float (*Asd)[BM] = reinterpret_cast<float(*)[BM]>(shbuf + d * SH_AS_STRIDE);
#pragma unroll
            for (int i = 0; i < 4; i++) {
                int idx = tid + i * 256;
                int kk = idx / BM, m = idx % BM;
                int r = rowBase + m;
                Asd[kk][m] = (r < n) ? A[(size_t)(k0 + kk) * NMAX + r] : 0.f;
            }
        }
#pragma unroll
        for (int i = 0; i < 4; i++) {
            int idx = tid + i * 256;
            int kk = idx / BN, j = idx % BN;
            Bs[kk][j] = lin1[(k0 + kk) * CC + colBase + j];
        }
        __syncthreads();
#pragma unroll
        for (int kk = 0; kk < BK; kk++) {
            ulonglong2 bv = *reinterpret_cast<const ulonglong2*>(&Bs[kk][tc * 4]);
#pragma unroll
            for (int d = 0; d < 3; d++) {
                const float* Asd = shbuf + d * SH_AS_STRIDE + kk * BM;
                float4 av = *reinterpret_cast<const float4*>(&Asd[tr * 4]);
                u64 a2[4];
                SPLAT2(a2[0], av.x); SPLAT2(a2[1], av.y);
                SPLAT2(a2[2], av.z); SPLAT2(a2[3], av.w);
#pragma unroll
                for (int i = 0; i < 4; i++) {
                    FMA2(acc[d][i][0], a2[i], bv.x, acc[d][i][0]);
                    FMA2(acc[d][i][1], a2[i], bv.y, acc[d][i][1]);
                }
            }
        }
        __syncthreads();
    }

#pragma unroll
    for (int i = 0; i < 4; i++) {
        int r = rowBase + tr * 4 + i;
        if (r >= n) continue;
        int b = d_nodeC[r];
        float f[12];
#pragma unroll
        for (int d = 0; d < 3; d++) {
            float l0, h0, l1, h1;
            UNPACK2(l0, h0, acc[d][i][0]);
            UNPACK2(l1, h1, acc[d][i][1]);
            f[0 * 3 + d] = l0; f[1 * 3 + d] = h0;
            f[2 * 3 + d] = l1; f[3 * 3 + d] = h1;
        }
        size_t base = (size_t)b * 512 + CC + (size_t)(colBase + tc * 4) * 3;
#pragma unroll
        for (int q = 0; q < 3; q++) {
            float4 scv = *reinterpret_cast<const float4*>(&sc[base + q * 4]);
            float4 ov = make_float4(f[q * 4 + 0] * INV_SQRT_C + scv.x,
                                    f[q * 4 + 1] * INV_SQRT_C + scv.y,
                                    f[q * 4 + 2] * INV_SQRT_C + scv.z,
                                    f[q * 4 + 3] * INV_SQRT_C + scv.w);
            *reinterpret_cast<float4*>(&out[base + q * 4]) = ov;
        }
    }
}

__global__ __launch_bounds__(256) void k_lin(const float* __restrict__ lin0,
                                             const float* __restrict__ lin1,
                                             const float* __restrict__ sc,
                                             float* __restrict__ out, int n) {
    __shared__ __align__(16) float shbuf[SH_BS_OFF + BK * BN];  // 16 KB
    if (blockIdx.z == 0) lin0_body(shbuf, lin0, sc, out, n);
    else                 lin1_body(shbuf, lin1, sc, out, n);
}

// ---------------------------------------------------------------- launch
extern "C" void kernel_launch(void* const* d_in, const int* in_sizes, int n_in,
                              void* d_out, int out_size) {
    const float* node_feats = (const float*)d_in[0];
    const float* node_attrs = (const float*)d_in[1];
    const float* sc         = (const float*)d_in[2];
    const float* U3_0 = (const float*)d_in[3];
    const float* U2_0 = (const float*)d_in[4];
    const float* U1_0 = (const float*)d_in[5];
    const float* w3_0 = (const float*)d_in[6];
    const float* w2_0 = (const float*)d_in[7];
    const float* w1_0 = (const float*)d_in[8];
    const float* U3_1 = (const float*)d_in[9];
    const float* U2_1 = (const float*)d_in[10];
    const float* U1_1 = (const float*)d_in[11];
    const float* w3_1 = (const float*)d_in[12];
    const float* w2_1 = (const float*)d_in[13];
    const float* w1_1 = (const float*)d_in[14];
    const float* lin_w0 = (const float*)d_in[15];
    const float* lin_w1 = (const float*)d_in[16];

    int n = in_sizes[0] / (CC * LL);

    k_init<<<1, 32>>>();
    k_assign<<<(n + 255) / 256, 256>>>(node_attrs, n);

    dim3 gc((MTOT + MCH - 1) / MCH, EE);
    k_coeffs<<<gc, 128>>>(U3_0, U2_0, U1_0, w3_0, w2_0, w1_0,
                          U3_1, U2_1, U1_1, w3_1, w2_1, w1_1);

    int maxT = (n + TILE - 1) / TILE + EE;
    k_main<<<dim3(CC / 4, maxT), 128>>>(node_feats);

    dim3 gl(CC / BN, (n + BM - 1) / BM, 2);
    k_lin<<<gl, 256>>>(lin_w0, lin_w1, sc, (float*)d_out, n);
}